// round 8
// baseline (speedup 1.0000x reference)
#include <cuda_runtime.h>
#include <math.h>

#define EPSV 1e-5f
#define HW   65536
#define CCH  64
#define NB   8
#define TP   128

// ---------------- scratch (device globals; no runtime allocation) ----------
__device__ float    g_sumx[2*NB*CCH];
__device__ unsigned g_cmax[2*NB*CCH];
__device__ unsigned g_kmax[2*NB];
__device__ float    g_klog[2*NB*HW];     // 4 MB
__device__ float    g_fea [2*NB*CCH];
__device__ float    g_Z   [2*NB];
__device__ float    g_avg [2*NB*CCH];
__device__ float    g_msm [2*NB*CCH];
__device__ float    g_gate[2*NB*CCH];
__device__ float    g_half[2*NB*HW];     // 4 MB
__device__ float    g_keywf[CCH];
__device__ float    g_convwt[CCH*CCH];   // conv_w transposed: [c][o]
__device__ float    g_valwt[CCH*CCH];    // val_w transposed + BN-scaled: [c][o]
__device__ float    g_valoff[CCH];
__device__ float    g_sc[4];             // keyoff, hw0, hw1, hoff

typedef unsigned long long ull;

// ---- f32x2 packed math (FFMA2 — only reachable via PTX) -------------------
__device__ __forceinline__ ull pack2(float a, float b) {
    ull r; asm("mov.b64 %0, {%1, %2};" : "=l"(r) : "f"(a), "f"(b)); return r;
}
__device__ __forceinline__ ull fma2(ull a, ull b, ull c) {
    ull d; asm("fma.rn.f32x2 %0, %1, %2, %3;" : "=l"(d) : "l"(a), "l"(b), "l"(c)); return d;
}
__device__ __forceinline__ float2 unpack2(ull v) {
    float2 f; asm("mov.b64 {%0, %1}, %2;" : "=f"(f.x), "=f"(f.y) : "l"(v)); return f;
}

// ordered-int encoding for float atomicMax
__device__ __forceinline__ unsigned ordf(float f) {
    unsigned u = __float_as_uint(f);
    return (u & 0x80000000u) ? ~u : (u | 0x80000000u);
}
__device__ __forceinline__ float deord(unsigned u) {
    u = (u & 0x80000000u) ? (u & 0x7fffffffu) : ~u;
    return __uint_as_float(u);
}
__device__ __forceinline__ float siluf(float z) {
    return __fdividef(z, 1.f + __expf(-z));
}

// ---------------- init: zero accumulators + fold BN + transpose weights ----
__global__ void k_init(const float* conv_w,
                       const float* key_w, const float* key_g, const float* key_b,
                       const float* key_m, const float* key_v,
                       const float* val_w, const float* val_g, const float* val_b,
                       const float* val_m, const float* val_v,
                       const float* half_w, const float* half_g, const float* half_b,
                       const float* half_m, const float* half_v) {
    int t = threadIdx.x;
    for (int i = t; i < 2*NB*CCH; i += blockDim.x) { g_sumx[i] = 0.f; g_cmax[i] = 0u; g_fea[i] = 0.f; }
    for (int i = t; i < 2*NB; i += blockDim.x) { g_kmax[i] = 0u; g_Z[i] = 0.f; }
    if (t < CCH) {
        int o = t;
        float ks = key_g[0] * rsqrtf(key_v[0] + EPSV);
        g_keywf[o] = key_w[o] * ks;
        float vs = val_g[o] * rsqrtf(val_v[o] + EPSV);
        g_valoff[o] = val_b[o] - val_m[o] * vs;
        for (int c = 0; c < CCH; c++) {
            g_valwt[c*CCH + o]  = val_w[o*CCH + c] * vs;
            g_convwt[c*CCH + o] = conv_w[o*CCH + c];
        }
        if (o == 0) g_sc[0] = key_b[0] - key_m[0] * ks;
        if (o == 1) {
            float hs = half_g[0] * rsqrtf(half_v[0] + EPSV);
            g_sc[1] = half_w[0] * hs;
            g_sc[2] = half_w[1] * hs;
            g_sc[3] = half_b[0] - half_m[0] * hs;
        }
    }
}

// ---------------- pass1: conv_w GEMM -> channel max; x sums; key logits ----
// 256 threads, 64x128 tile. og=t>>5 owns channels 8og..8og+7 (contiguous),
// pg=t&31 owns pixels 4pg..4pg+3 (contiguous). Warp == one og group.
__global__ void __launch_bounds__(256, 4)
k_pass1(const float* __restrict__ xr, const float* __restrict__ xi) {
    extern __shared__ float sm[];
    float* Xs  = sm;             // 64*128
    float* Wt  = sm + 8192;      // 64*64, k-major [c][o]
    float* kw  = Wt + 4096;      // 64
    float* red = kw + 64;        // 8
    int s = blockIdx.z, n = blockIdx.y;
    int p0 = blockIdx.x * TP;
    const float* x = (s == 0 ? xr : xi) + (size_t)n * CCH * HW + p0;
    int t = threadIdx.x;

    for (int i4 = t; i4 < 2048; i4 += 256) {
        int c = i4 >> 5, pq = i4 & 31;
        *(float4*)(Xs + c*TP + pq*4) = *(const float4*)(x + (size_t)c*HW + pq*4);
    }
    for (int i = t; i < 4096; i += 256) Wt[i] = g_convwt[i];
    if (t < 64) kw[t] = g_keywf[t];
    __syncthreads();

    int og = t >> 5, pg = t & 31;
    const float* Wb = Wt + 8*og;
    const float* Xb = Xs + 4*pg;

    ull acc2[8][2];
    #pragma unroll
    for (int i = 0; i < 8; i++) { acc2[i][0] = 0ULL; acc2[i][1] = 0ULL; }

    #pragma unroll 8
    for (int c = 0; c < 64; c++) {
        float4 wa  = *(const float4*)(Wb + c*64);
        float4 wb4 = *(const float4*)(Wb + c*64 + 4);
        ulonglong2 xv = *(const ulonglong2*)(Xb + c*TP);
        float wv[8] = {wa.x, wa.y, wa.z, wa.w, wb4.x, wb4.y, wb4.z, wb4.w};
        #pragma unroll
        for (int i = 0; i < 8; i++) {
            ull wp = pack2(wv[i], wv[i]);
            acc2[i][0] = fma2(wp, xv.x, acc2[i][0]);
            acc2[i][1] = fma2(wp, xv.y, acc2[i][1]);
        }
    }

    int base = (s*NB + n) * CCH;
    // per-channel max over pixels (bias added later)
    #pragma unroll
    for (int i = 0; i < 8; i++) {
        float2 f0 = unpack2(acc2[i][0]), f1 = unpack2(acc2[i][1]);
        float m = fmaxf(fmaxf(f0.x, f0.y), fmaxf(f1.x, f1.y));
        #pragma unroll
        for (int k = 16; k >= 1; k >>= 1) m = fmaxf(m, __shfl_xor_sync(0xffffffffu, m, k));
        if (pg == 0) atomicMax(&g_cmax[base + 8*og + i], ordf(m));
    }
    // per-channel sums of x (exact mean path)
    #pragma unroll
    for (int i = 0; i < 8; i++) {
        int c = 8*og + i;
        float4 xv = *(const float4*)(Xs + c*TP + 4*pg);
        float ssum = (xv.x + xv.y) + (xv.z + xv.w);
        #pragma unroll
        for (int k = 16; k >= 1; k >>= 1) ssum += __shfl_xor_sync(0xffffffffu, ssum, k);
        if (pg == 0) atomicAdd(&g_sumx[base + c], ssum);
    }
    // key logit: two threads per pixel, split channel halves
    int p = t >> 1, h = t & 1;
    float z = 0.f;
    #pragma unroll 8
    for (int c = 32*h; c < 32*h + 32; c++) z = fmaf(kw[c], Xs[c*TP + p], z);
    z += __shfl_xor_sync(0xffffffffu, z, 1);
    z += g_sc[0];
    float kl = siluf(z);
    if (h == 0) g_klog[(size_t)(s*NB + n) * HW + p0 + p] = kl;
    float km = (h == 0) ? kl : -1e30f;
    #pragma unroll
    for (int k = 16; k >= 1; k >>= 1) km = fmaxf(km, __shfl_xor_sync(0xffffffffu, km, k));
    if ((t & 31) == 0) red[t >> 5] = km;
    __syncthreads();
    if (t == 0) {
        float m = red[0];
        #pragma unroll
        for (int w = 1; w < 8; w++) m = fmaxf(m, red[w]);
        atomicMax(&g_kmax[s*NB + n], ordf(m));
    }
}

// ---------------- mid: channel softmaxes (avg from sums, max from cmax) ----
__device__ __forceinline__ float blockmax64(float v, float* tmp) {
    tmp[threadIdx.x] = v; __syncthreads();
    for (int k = 32; k >= 1; k >>= 1) {
        if (threadIdx.x < k) tmp[threadIdx.x] = fmaxf(tmp[threadIdx.x], tmp[threadIdx.x + k]);
        __syncthreads();
    }
    float r = tmp[0]; __syncthreads(); return r;
}
__device__ __forceinline__ float blocksum64(float v, float* tmp) {
    tmp[threadIdx.x] = v; __syncthreads();
    for (int k = 32; k >= 1; k >>= 1) {
        if (threadIdx.x < k) tmp[threadIdx.x] += tmp[threadIdx.x + k];
        __syncthreads();
    }
    float r = tmp[0]; __syncthreads(); return r;
}

__global__ void k_mid(const float* __restrict__ conv_w, const float* __restrict__ conv_b) {
    int s = blockIdx.x, n = blockIdx.y, o = threadIdx.x;
    __shared__ float sx[64], tmp[64];
    int base = (s*NB + n) * CCH;
    sx[o] = g_sumx[base + o] * (1.f / (float)HW);
    __syncthreads();
    float mean = conv_b[o];
    for (int c = 0; c < 64; c++) mean = fmaf(sx[c], conv_w[o*64 + c], mean);
    float mx = deord(g_cmax[base + o]) + conv_b[o];

    float m1 = blockmax64(mean, tmp);
    float e1 = expf(mean - m1);
    float s1 = blocksum64(e1, tmp);
    g_avg[base + o] = e1 / s1;

    float m2 = blockmax64(mx, tmp);
    float e2 = expf(mx - m2);
    float s2 = blocksum64(e2, tmp);
    g_msm[base + o] = e2 / s2;
}

// ---------------- pass2: val GEMM + fused fea/Z/half -----------------------
__global__ void __launch_bounds__(256, 4)
k_pass2(const float* __restrict__ xr, const float* __restrict__ xi) {
    extern __shared__ float sm[];
    float* Xs   = sm;            // 8192, reused as V after GEMM
    float* Wt   = sm + 8192;     // 4096
    float* voff = Wt + 4096;     // 64
    float* av   = voff + 64;     // 64
    float* mv   = av + 64;       // 64
    float* es   = mv + 64;       // 128
    float* red  = es + 128;      // 8
    int sx = blockIdx.z, n = blockIdx.y, so = 1 - sx;   // V of side sx feeds output side so
    int p0 = blockIdx.x * TP;
    int t = threadIdx.x;
    const float* x = (sx == 0 ? xr : xi) + (size_t)n * CCH * HW + p0;

    for (int i4 = t; i4 < 2048; i4 += 256) {
        int c = i4 >> 5, pq = i4 & 31;
        *(float4*)(Xs + c*TP + pq*4) = *(const float4*)(x + (size_t)c*HW + pq*4);
    }
    for (int i = t; i < 4096; i += 256) Wt[i] = g_valwt[i];
    if (t < 64) {
        voff[t] = g_valoff[t];
        int b2 = (so*NB + n) * CCH;
        av[t] = g_avg[b2 + t];
        mv[t] = g_msm[b2 + t];
    }
    __syncthreads();

    int og = t >> 5, pg = t & 31;
    const float* Wb = Wt + 8*og;
    const float* Xb = Xs + 4*pg;

    ull acc2[8][2];
    #pragma unroll
    for (int i = 0; i < 8; i++) { acc2[i][0] = 0ULL; acc2[i][1] = 0ULL; }

    #pragma unroll 8
    for (int c = 0; c < 64; c++) {
        float4 wa  = *(const float4*)(Wb + c*64);
        float4 wb4 = *(const float4*)(Wb + c*64 + 4);
        ulonglong2 xv = *(const ulonglong2*)(Xb + c*TP);
        float wv[8] = {wa.x, wa.y, wa.z, wa.w, wb4.x, wb4.y, wb4.z, wb4.w};
        #pragma unroll
        for (int i = 0; i < 8; i++) {
            ull wp = pack2(wv[i], wv[i]);
            acc2[i][0] = fma2(wp, xv.x, acc2[i][0]);
            acc2[i][1] = fma2(wp, xv.y, acc2[i][1]);
        }
    }
    __syncthreads();   // done reading Xs; overwrite with V

    #pragma unroll
    for (int i = 0; i < 8; i++) {
        int c = 8*og + i;
        float off = voff[c];
        float2 f0 = unpack2(acc2[i][0]), f1 = unpack2(acc2[i][1]);
        float4 o4;
        o4.x = siluf(f0.x + off); o4.y = siluf(f0.y + off);
        o4.z = siluf(f1.x + off); o4.w = siluf(f1.y + off);
        *(float4*)(Xs + c*TP + 4*pg) = o4;
    }
    __syncthreads();

    // per-pixel: key weight e, half output (two threads per pixel)
    int p = t >> 1, h = t & 1;
    float kmaxv = deord(g_kmax[so*NB + n]);
    float kl = g_klog[(size_t)(so*NB + n) * HW + p0 + p];
    float e = __expf(kl - kmaxv);
    if (h == 0) es[p] = e;
    float sa = 0.f, smx = 0.f;
    #pragma unroll 8
    for (int c = 32*h; c < 32*h + 32; c++) {
        float vv = Xs[c*TP + p];
        sa  = fmaf(av[c], vv, sa);
        smx = fmaf(mv[c], vv, smx);
    }
    sa  += __shfl_xor_sync(0xffffffffu, sa, 1);
    smx += __shfl_xor_sync(0xffffffffu, smx, 1);
    if (h == 0) {
        float pre = g_sc[1]*sa + g_sc[2]*smx + g_sc[3];
        g_half[(size_t)(so*NB + n) * HW + p0 + p] = siluf(pre);
    }

    float zc = (h == 0) ? e : 0.f;
    #pragma unroll
    for (int k = 16; k >= 1; k >>= 1) zc += __shfl_xor_sync(0xffffffffu, zc, k);
    if ((t & 31) == 0) red[t >> 5] = zc;
    __syncthreads();    // also makes es[] visible block-wide
    if (t == 0) {
        float zs = 0.f;
        #pragma unroll
        for (int w = 0; w < 8; w++) zs += red[w];
        atomicAdd(&g_Z[so*NB + n], zs);
    }

    // fea[c] += sum_p V[c][p]*e[p]  (f32x2, LDS.128 on V and es)
    ulonglong2 ev = *(const ulonglong2*)(es + 4*pg);
    #pragma unroll
    for (int i = 0; i < 8; i++) {
        int c = 8*og + i;
        ulonglong2 vv = *(const ulonglong2*)(Xs + c*TP + 4*pg);
        ull fs2 = fma2(vv.x, ev.x, 0ULL);
        fs2 = fma2(vv.y, ev.y, fs2);
        float2 f = unpack2(fs2);
        float fs = f.x + f.y;
        #pragma unroll
        for (int k = 16; k >= 1; k >>= 1) fs += __shfl_xor_sync(0xffffffffu, fs, k);
        if (pg == 0) atomicAdd(&g_fea[(so*NB + n)*CCH + c], fs);
    }
}

// ---------------- gate: fea/Z -> convb -> LN -> sigmoid --------------------
__global__ void k_gate(const float* __restrict__ convb_w,
                       const float* __restrict__ ln_g, const float* __restrict__ ln_b) {
    int so = blockIdx.x, n = blockIdx.y, o = threadIdx.x;
    __shared__ float ff[64], tmp[64];
    int base = (so*NB + n) * CCH;
    float Z = g_Z[so*NB + n];
    ff[o] = g_fea[base + o] / Z;
    __syncthreads();
    float v = 0.f;
    for (int c = 0; c < 64; c++) v = fmaf(ff[c], convb_w[o*64 + c], v);
    float mu = blocksum64(v, tmp) * (1.f/64.f);
    float d = v - mu;
    float var = blocksum64(d*d, tmp) * (1.f/64.f);
    float gz = d * rsqrtf(var + EPSV) * ln_g[o] + ln_b[o];
    g_gate[base + o] = 1.f / (1.f + expf(-gz));
}

// ---------------- pass3: out = gate*half + me ------------------------------
__global__ void k_pass3(const float* __restrict__ xr, const float* __restrict__ xi,
                        float* __restrict__ out) {
    size_t g = (size_t)blockIdx.x * blockDim.x + threadIdx.x;  // float4 index
    int cl = (int)(g >> 14);          // s*512 + n*64 + c
    int p4 = (int)(g & 16383);
    int s = cl >> 9, n = (cl >> 6) & 7, c = cl & 63;
    float gate = g_gate[(s*NB + n)*CCH + c];
    float4 h4 = *(const float4*)(g_half + ((size_t)(s*NB + n) << 16) + (size_t)p4*4);
    const float* x = (s == 0 ? xr : xi);
    float4 m4 = *(const float4*)(x + (((size_t)n*64 + c) << 16) + (size_t)p4*4);
    float4 o4;
    o4.x = fmaf(gate, h4.x, m4.x);
    o4.y = fmaf(gate, h4.y, m4.y);
    o4.z = fmaf(gate, h4.z, m4.z);
    o4.w = fmaf(gate, h4.w, m4.w);
    *(float4*)(out + (g << 2)) = o4;
}

// ---------------- launch ---------------------------------------------------
extern "C" void kernel_launch(void* const* d_in, const int* in_sizes, int n_in,
                              void* d_out, int out_size) {
    const float* rgb    = (const float*)d_in[0];
    const float* ir     = (const float*)d_in[1];
    const float* conv_w = (const float*)d_in[2];
    const float* conv_b = (const float*)d_in[3];
    const float* key_w  = (const float*)d_in[4];
    const float* key_g  = (const float*)d_in[5];
    const float* key_b  = (const float*)d_in[6];
    const float* key_m  = (const float*)d_in[7];
    const float* key_v  = (const float*)d_in[8];
    const float* val_w  = (const float*)d_in[9];
    const float* val_g  = (const float*)d_in[10];
    const float* val_b  = (const float*)d_in[11];
    const float* val_m  = (const float*)d_in[12];
    const float* val_v  = (const float*)d_in[13];
    const float* convb_w= (const float*)d_in[14];
    const float* half_w = (const float*)d_in[15];
    const float* half_g = (const float*)d_in[16];
    const float* half_b = (const float*)d_in[17];
    const float* half_m = (const float*)d_in[18];
    const float* half_v = (const float*)d_in[19];
    const float* ln_g   = (const float*)d_in[20];
    const float* ln_b   = (const float*)d_in[21];
    float* out = (float*)d_out;

    const int SMEM1 = (8192 + 4096 + 64 + 8) * 4;
    const int SMEM2 = (8192 + 4096 + 64 + 64 + 64 + 128 + 8) * 4;
    cudaFuncSetAttribute(k_pass1, cudaFuncAttributeMaxDynamicSharedMemorySize, SMEM1);
    cudaFuncSetAttribute(k_pass2, cudaFuncAttributeMaxDynamicSharedMemorySize, SMEM2);

    k_init<<<1, 256>>>(conv_w, key_w, key_g, key_b, key_m, key_v,
                       val_w, val_g, val_b, val_m, val_v,
                       half_w, half_g, half_b, half_m, half_v);
    dim3 gP(HW / TP, NB, 2);
    k_pass1<<<gP, 256, SMEM1>>>(rgb, ir);
    k_mid<<<dim3(2, NB), 64>>>(conv_w, conv_b);
    k_pass2<<<gP, 256, SMEM2>>>(rgb, ir);
    k_gate<<<dim3(2, NB), 64>>>(convb_w, ln_g, ln_b);
    k_pass3<<<65536, 256>>>(rgb, ir, out);
}

// round 9
// speedup vs baseline: 1.0072x; 1.0072x over previous
#include <cuda_runtime.h>
#include <math.h>

#define EPSV 1e-5f
#define HW   65536
#define CCH  64
#define NB   8
#define TP   128

// ---------------- scratch (device globals; no runtime allocation) ----------
__device__ float    g_sumx[2*NB*CCH];
__device__ unsigned g_cmax[2*NB*CCH];
__device__ unsigned g_kmax[2*NB];
__device__ float    g_klog[2*NB*HW];     // 4 MB
__device__ float    g_fea [2*NB*CCH];
__device__ float    g_Z   [2*NB];
__device__ float    g_avg [2*NB*CCH];
__device__ float    g_msm [2*NB*CCH];
__device__ float    g_gate[2*NB*CCH];
__device__ float    g_half[2*NB*HW];     // 4 MB
__device__ float    g_keywf[CCH];
__device__ float    g_convwt[CCH*CCH];   // conv_w transposed: [c][o]
__device__ float    g_valwt[CCH*CCH];    // val_w transposed + BN-scaled: [c][o]
__device__ float    g_valoff[CCH];
__device__ float    g_sc[4];             // keyoff, hw0, hw1, hoff

typedef unsigned long long ull;

// ---- f32x2 packed math (FFMA2 — only reachable via PTX) -------------------
__device__ __forceinline__ ull pack2(float a, float b) {
    ull r; asm("mov.b64 %0, {%1, %2};" : "=l"(r) : "f"(a), "f"(b)); return r;
}
__device__ __forceinline__ ull fma2(ull a, ull b, ull c) {
    ull d; asm("fma.rn.f32x2 %0, %1, %2, %3;" : "=l"(d) : "l"(a), "l"(b), "l"(c)); return d;
}
__device__ __forceinline__ float2 unpack2(ull v) {
    float2 f; asm("mov.b64 {%0, %1}, %2;" : "=f"(f.x), "=f"(f.y) : "l"(v)); return f;
}

// ordered-int encoding for float atomicMax
__device__ __forceinline__ unsigned ordf(float f) {
    unsigned u = __float_as_uint(f);
    return (u & 0x80000000u) ? ~u : (u | 0x80000000u);
}
__device__ __forceinline__ float deord(unsigned u) {
    u = (u & 0x80000000u) ? (u & 0x7fffffffu) : ~u;
    return __uint_as_float(u);
}
__device__ __forceinline__ float siluf(float z) {
    return __fdividef(z, 1.f + __expf(-z));
}

// ---------------- init: zero accumulators + fold BN + transpose weights ----
__global__ void k_init(const float* conv_w,
                       const float* key_w, const float* key_g, const float* key_b,
                       const float* key_m, const float* key_v,
                       const float* val_w, const float* val_g, const float* val_b,
                       const float* val_m, const float* val_v,
                       const float* half_w, const float* half_g, const float* half_b,
                       const float* half_m, const float* half_v) {
    int t = threadIdx.x;
    for (int i = t; i < 2*NB*CCH; i += blockDim.x) { g_sumx[i] = 0.f; g_cmax[i] = 0u; g_fea[i] = 0.f; }
    for (int i = t; i < 2*NB; i += blockDim.x) { g_kmax[i] = 0u; g_Z[i] = 0.f; }
    if (t < CCH) {
        int o = t;
        float ks = key_g[0] * rsqrtf(key_v[0] + EPSV);
        g_keywf[o] = key_w[o] * ks;
        float vs = val_g[o] * rsqrtf(val_v[o] + EPSV);
        g_valoff[o] = val_b[o] - val_m[o] * vs;
        for (int c = 0; c < CCH; c++) {
            g_valwt[c*CCH + o]  = val_w[o*CCH + c] * vs;
            g_convwt[c*CCH + o] = conv_w[o*CCH + c];
        }
        if (o == 0) g_sc[0] = key_b[0] - key_m[0] * ks;
        if (o == 1) {
            float hs = half_g[0] * rsqrtf(half_v[0] + EPSV);
            g_sc[1] = half_w[0] * hs;
            g_sc[2] = half_w[1] * hs;
            g_sc[3] = half_b[0] - half_m[0] * hs;
        }
    }
}

// ---------------- pass1: conv_w GEMM -> channel max; x sums; key logits ----
// 256 threads, 64x128 tile. og=t>>5 owns channels 8og..8og+7 (contiguous),
// pg=t&31 owns pixels 4pg..4pg+3 (contiguous). Warp == one og group.
__global__ void __launch_bounds__(256, 4)
k_pass1(const float* __restrict__ xr, const float* __restrict__ xi) {
    extern __shared__ float sm[];
    float* Xs  = sm;             // 64*128
    float* Wt  = sm + 8192;      // 64*64, k-major [c][o]
    float* kw  = Wt + 4096;      // 64
    float* red = kw + 64;        // 8
    int s = blockIdx.z, n = blockIdx.y;
    int p0 = blockIdx.x * TP;
    const float* x = (s == 0 ? xr : xi) + (size_t)n * CCH * HW + p0;
    int t = threadIdx.x;

    for (int i4 = t; i4 < 2048; i4 += 256) {
        int c = i4 >> 5, pq = i4 & 31;
        *(float4*)(Xs + c*TP + pq*4) = *(const float4*)(x + (size_t)c*HW + pq*4);
    }
    for (int i = t; i < 4096; i += 256) Wt[i] = g_convwt[i];
    if (t < 64) kw[t] = g_keywf[t];
    __syncthreads();

    int og = t >> 5, pg = t & 31;
    const float* Wb = Wt + 8*og;
    const float* Xb = Xs + 4*pg;

    ull acc2[8][2];
    #pragma unroll
    for (int i = 0; i < 8; i++) { acc2[i][0] = 0ULL; acc2[i][1] = 0ULL; }

    #pragma unroll 8
    for (int c = 0; c < 64; c++) {
        float4 wa  = *(const float4*)(Wb + c*64);
        float4 wb4 = *(const float4*)(Wb + c*64 + 4);
        ulonglong2 xv = *(const ulonglong2*)(Xb + c*TP);
        float wv[8] = {wa.x, wa.y, wa.z, wa.w, wb4.x, wb4.y, wb4.z, wb4.w};
        #pragma unroll
        for (int i = 0; i < 8; i++) {
            ull wp = pack2(wv[i], wv[i]);
            acc2[i][0] = fma2(wp, xv.x, acc2[i][0]);
            acc2[i][1] = fma2(wp, xv.y, acc2[i][1]);
        }
    }

    int base = (s*NB + n) * CCH;
    // per-channel max over pixels (bias added later)
    #pragma unroll
    for (int i = 0; i < 8; i++) {
        float2 f0 = unpack2(acc2[i][0]), f1 = unpack2(acc2[i][1]);
        float m = fmaxf(fmaxf(f0.x, f0.y), fmaxf(f1.x, f1.y));
        #pragma unroll
        for (int k = 16; k >= 1; k >>= 1) m = fmaxf(m, __shfl_xor_sync(0xffffffffu, m, k));
        if (pg == 0) atomicMax(&g_cmax[base + 8*og + i], ordf(m));
    }
    // per-channel sums of x (exact mean path)
    #pragma unroll
    for (int i = 0; i < 8; i++) {
        int c = 8*og + i;
        float4 xv = *(const float4*)(Xs + c*TP + 4*pg);
        float ssum = (xv.x + xv.y) + (xv.z + xv.w);
        #pragma unroll
        for (int k = 16; k >= 1; k >>= 1) ssum += __shfl_xor_sync(0xffffffffu, ssum, k);
        if (pg == 0) atomicAdd(&g_sumx[base + c], ssum);
    }
    // key logit: two threads per pixel, split channel halves
    int p = t >> 1, h = t & 1;
    float z = 0.f;
    #pragma unroll 8
    for (int c = 32*h; c < 32*h + 32; c++) z = fmaf(kw[c], Xs[c*TP + p], z);
    z += __shfl_xor_sync(0xffffffffu, z, 1);
    z += g_sc[0];
    float kl = siluf(z);
    if (h == 0) g_klog[(size_t)(s*NB + n) * HW + p0 + p] = kl;
    float km = (h == 0) ? kl : -1e30f;
    #pragma unroll
    for (int k = 16; k >= 1; k >>= 1) km = fmaxf(km, __shfl_xor_sync(0xffffffffu, km, k));
    if ((t & 31) == 0) red[t >> 5] = km;
    __syncthreads();
    if (t == 0) {
        float m = red[0];
        #pragma unroll
        for (int w = 1; w < 8; w++) m = fmaxf(m, red[w]);
        atomicMax(&g_kmax[s*NB + n], ordf(m));
    }
}

// ---------------- mid: channel softmaxes (avg from sums, max from cmax) ----
__device__ __forceinline__ float blockmax64(float v, float* tmp) {
    tmp[threadIdx.x] = v; __syncthreads();
    for (int k = 32; k >= 1; k >>= 1) {
        if (threadIdx.x < k) tmp[threadIdx.x] = fmaxf(tmp[threadIdx.x], tmp[threadIdx.x + k]);
        __syncthreads();
    }
    float r = tmp[0]; __syncthreads(); return r;
}
__device__ __forceinline__ float blocksum64(float v, float* tmp) {
    tmp[threadIdx.x] = v; __syncthreads();
    for (int k = 32; k >= 1; k >>= 1) {
        if (threadIdx.x < k) tmp[threadIdx.x] += tmp[threadIdx.x + k];
        __syncthreads();
    }
    float r = tmp[0]; __syncthreads(); return r;
}

__global__ void k_mid(const float* __restrict__ conv_w, const float* __restrict__ conv_b) {
    int s = blockIdx.x, n = blockIdx.y, o = threadIdx.x;
    __shared__ float sx[64], tmp[64];
    int base = (s*NB + n) * CCH;
    sx[o] = g_sumx[base + o] * (1.f / (float)HW);
    __syncthreads();
    float mean = conv_b[o];
    for (int c = 0; c < 64; c++) mean = fmaf(sx[c], conv_w[o*64 + c], mean);
    float mx = deord(g_cmax[base + o]) + conv_b[o];

    float m1 = blockmax64(mean, tmp);
    float e1 = expf(mean - m1);
    float s1 = blocksum64(e1, tmp);
    g_avg[base + o] = e1 / s1;

    float m2 = blockmax64(mx, tmp);
    float e2 = expf(mx - m2);
    float s2 = blocksum64(e2, tmp);
    g_msm[base + o] = e2 / s2;
}

// ---------------- pass2: val GEMM + fused fea/Z/half -----------------------
__global__ void __launch_bounds__(256, 4)
k_pass2(const float* __restrict__ xr, const float* __restrict__ xi) {
    extern __shared__ float sm[];
    float* Xs   = sm;            // 8192, reused as V after GEMM
    float* Wt   = sm + 8192;     // 4096
    float* voff = Wt + 4096;     // 64
    float* av   = voff + 64;     // 64
    float* mv   = av + 64;       // 64
    float* es   = mv + 64;       // 128
    float* red  = es + 128;      // 8
    int sx = blockIdx.z, n = blockIdx.y, so = 1 - sx;   // V of side sx feeds output side so
    int p0 = blockIdx.x * TP;
    int t = threadIdx.x;
    const float* x = (sx == 0 ? xr : xi) + (size_t)n * CCH * HW + p0;

    for (int i4 = t; i4 < 2048; i4 += 256) {
        int c = i4 >> 5, pq = i4 & 31;
        *(float4*)(Xs + c*TP + pq*4) = *(const float4*)(x + (size_t)c*HW + pq*4);
    }
    for (int i = t; i < 4096; i += 256) Wt[i] = g_valwt[i];
    if (t < 64) {
        voff[t] = g_valoff[t];
        int b2 = (so*NB + n) * CCH;
        av[t] = g_avg[b2 + t];
        mv[t] = g_msm[b2 + t];
    }
    __syncthreads();

    int og = t >> 5, pg = t & 31;
    const float* Wb = Wt + 8*og;
    const float* Xb = Xs + 4*pg;

    ull acc2[8][2];
    #pragma unroll
    for (int i = 0; i < 8; i++) { acc2[i][0] = 0ULL; acc2[i][1] = 0ULL; }

    #pragma unroll 8
    for (int c = 0; c < 64; c++) {
        float4 wa  = *(const float4*)(Wb + c*64);
        float4 wb4 = *(const float4*)(Wb + c*64 + 4);
        ulonglong2 xv = *(const ulonglong2*)(Xb + c*TP);
        float wv[8] = {wa.x, wa.y, wa.z, wa.w, wb4.x, wb4.y, wb4.z, wb4.w};
        #pragma unroll
        for (int i = 0; i < 8; i++) {
            ull wp = pack2(wv[i], wv[i]);
            acc2[i][0] = fma2(wp, xv.x, acc2[i][0]);
            acc2[i][1] = fma2(wp, xv.y, acc2[i][1]);
        }
    }
    __syncthreads();   // done reading Xs; overwrite with V

    #pragma unroll
    for (int i = 0; i < 8; i++) {
        int c = 8*og + i;
        float off = voff[c];
        float2 f0 = unpack2(acc2[i][0]), f1 = unpack2(acc2[i][1]);
        float4 o4;
        o4.x = siluf(f0.x + off); o4.y = siluf(f0.y + off);
        o4.z = siluf(f1.x + off); o4.w = siluf(f1.y + off);
        *(float4*)(Xs + c*TP + 4*pg) = o4;
    }
    __syncthreads();

    // per-pixel: key weight e, half output (two threads per pixel)
    int p = t >> 1, h = t & 1;
    float kmaxv = deord(g_kmax[so*NB + n]);
    float kl = g_klog[(size_t)(so*NB + n) * HW + p0 + p];
    float e = __expf(kl - kmaxv);
    if (h == 0) es[p] = e;
    float sa = 0.f, smx = 0.f;
    #pragma unroll 8
    for (int c = 32*h; c < 32*h + 32; c++) {
        float vv = Xs[c*TP + p];
        sa  = fmaf(av[c], vv, sa);
        smx = fmaf(mv[c], vv, smx);
    }
    sa  += __shfl_xor_sync(0xffffffffu, sa, 1);
    smx += __shfl_xor_sync(0xffffffffu, smx, 1);
    if (h == 0) {
        float pre = g_sc[1]*sa + g_sc[2]*smx + g_sc[3];
        g_half[(size_t)(so*NB + n) * HW + p0 + p] = siluf(pre);
    }

    float zc = (h == 0) ? e : 0.f;
    #pragma unroll
    for (int k = 16; k >= 1; k >>= 1) zc += __shfl_xor_sync(0xffffffffu, zc, k);
    if ((t & 31) == 0) red[t >> 5] = zc;
    __syncthreads();    // also makes es[] visible block-wide
    if (t == 0) {
        float zs = 0.f;
        #pragma unroll
        for (int w = 0; w < 8; w++) zs += red[w];
        atomicAdd(&g_Z[so*NB + n], zs);
    }

    // fea[c] += sum_p V[c][p]*e[p]  (f32x2, LDS.128 on V and es)
    ulonglong2 ev = *(const ulonglong2*)(es + 4*pg);
    #pragma unroll
    for (int i = 0; i < 8; i++) {
        int c = 8*og + i;
        ulonglong2 vv = *(const ulonglong2*)(Xs + c*TP + 4*pg);
        ull fs2 = fma2(vv.x, ev.x, 0ULL);
        fs2 = fma2(vv.y, ev.y, fs2);
        float2 f = unpack2(fs2);
        float fs = f.x + f.y;
        #pragma unroll
        for (int k = 16; k >= 1; k >>= 1) fs += __shfl_xor_sync(0xffffffffu, fs, k);
        if (pg == 0) atomicAdd(&g_fea[(so*NB + n)*CCH + c], fs);
    }
}

// ---------------- gate: fea/Z -> convb -> LN -> sigmoid --------------------
__global__ void k_gate(const float* __restrict__ convb_w,
                       const float* __restrict__ ln_g, const float* __restrict__ ln_b) {
    int so = blockIdx.x, n = blockIdx.y, o = threadIdx.x;
    __shared__ float ff[64], tmp[64];
    int base = (so*NB + n) * CCH;
    float Z = g_Z[so*NB + n];
    ff[o] = g_fea[base + o] / Z;
    __syncthreads();
    float v = 0.f;
    for (int c = 0; c < 64; c++) v = fmaf(ff[c], convb_w[o*64 + c], v);
    float mu = blocksum64(v, tmp) * (1.f/64.f);
    float d = v - mu;
    float var = blocksum64(d*d, tmp) * (1.f/64.f);
    float gz = d * rsqrtf(var + EPSV) * ln_g[o] + ln_b[o];
    g_gate[base + o] = 1.f / (1.f + expf(-gz));
}

// ---------------- pass3: out = gate*half + me ------------------------------
__global__ void k_pass3(const float* __restrict__ xr, const float* __restrict__ xi,
                        float* __restrict__ out) {
    size_t g = (size_t)blockIdx.x * blockDim.x + threadIdx.x;  // float4 index
    int cl = (int)(g >> 14);          // s*512 + n*64 + c
    int p4 = (int)(g & 16383);
    int s = cl >> 9, n = (cl >> 6) & 7, c = cl & 63;
    float gate = g_gate[(s*NB + n)*CCH + c];
    float4 h4 = *(const float4*)(g_half + ((size_t)(s*NB + n) << 16) + (size_t)p4*4);
    const float* x = (s == 0 ? xr : xi);
    float4 m4 = *(const float4*)(x + (((size_t)n*64 + c) << 16) + (size_t)p4*4);
    float4 o4;
    o4.x = fmaf(gate, h4.x, m4.x);
    o4.y = fmaf(gate, h4.y, m4.y);
    o4.z = fmaf(gate, h4.z, m4.z);
    o4.w = fmaf(gate, h4.w, m4.w);
    *(float4*)(out + (g << 2)) = o4;
}

// ---------------- launch ---------------------------------------------------
extern "C" void kernel_launch(void* const* d_in, const int* in_sizes, int n_in,
                              void* d_out, int out_size) {
    const float* rgb    = (const float*)d_in[0];
    const float* ir     = (const float*)d_in[1];
    const float* conv_w = (const float*)d_in[2];
    const float* conv_b = (const float*)d_in[3];
    const float* key_w  = (const float*)d_in[4];
    const float* key_g  = (const float*)d_in[5];
    const float* key_b  = (const float*)d_in[6];
    const float* key_m  = (const float*)d_in[7];
    const float* key_v  = (const float*)d_in[8];
    const float* val_w  = (const float*)d_in[9];
    const float* val_g  = (const float*)d_in[10];
    const float* val_b  = (const float*)d_in[11];
    const float* val_m  = (const float*)d_in[12];
    const float* val_v  = (const float*)d_in[13];
    const float* convb_w= (const float*)d_in[14];
    const float* half_w = (const float*)d_in[15];
    const float* half_g = (const float*)d_in[16];
    const float* half_b = (const float*)d_in[17];
    const float* half_m = (const float*)d_in[18];
    const float* half_v = (const float*)d_in[19];
    const float* ln_g   = (const float*)d_in[20];
    const float* ln_b   = (const float*)d_in[21];
    float* out = (float*)d_out;

    const int SMEM1 = (8192 + 4096 + 64 + 8) * 4;
    const int SMEM2 = (8192 + 4096 + 64 + 64 + 64 + 128 + 8) * 4;
    cudaFuncSetAttribute(k_pass1, cudaFuncAttributeMaxDynamicSharedMemorySize, SMEM1);
    cudaFuncSetAttribute(k_pass2, cudaFuncAttributeMaxDynamicSharedMemorySize, SMEM2);

    k_init<<<1, 256>>>(conv_w, key_w, key_g, key_b, key_m, key_v,
                       val_w, val_g, val_b, val_m, val_v,
                       half_w, half_g, half_b, half_m, half_v);
    dim3 gP(HW / TP, NB, 2);
    k_pass1<<<gP, 256, SMEM1>>>(rgb, ir);
    k_mid<<<dim3(2, NB), 64>>>(conv_w, conv_b);
    k_pass2<<<gP, 256, SMEM2>>>(rgb, ir);
    k_gate<<<dim3(2, NB), 64>>>(convb_w, ln_g, ln_b);
    k_pass3<<<65536, 256>>>(rgb, ir, out);
}

// round 12
// speedup vs baseline: 1.0717x; 1.0640x over previous
#include <cuda_runtime.h>
#include <math.h>
#include <stdint.h>

#define EPSV 1e-5f
#define HW   65536
#define CCH  64
#define NB   8
#define TP   128

// ---------------- scratch (device globals; no runtime allocation) ----------
__device__ float    g_sumx[2*NB*CCH];
__device__ unsigned g_cmax[2*NB*CCH];
__device__ unsigned g_kmax[2*NB];
__device__ float    g_klog[2*NB*HW];     // 4 MB
__device__ float    g_fea [2*NB*CCH];
__device__ float    g_Z   [2*NB];
__device__ float    g_avg [2*NB*CCH];
__device__ float    g_msm [2*NB*CCH];
__device__ float    g_gate[2*NB*CCH];
__device__ float    g_half[2*NB*HW];     // 4 MB
__device__ float    g_convw_r[CCH*CCH];  // conv_w, tf32-rounded, row-major [o][k]
__device__ float    g_valw_r[CCH*CCH];   // val_w*BNscale, tf32-rounded, [o][k]
__device__ float    g_keywf[CCH];
__device__ float    g_valoff[CCH];
__device__ float    g_sc[4];             // keyoff, hw0, hw1, hoff

// smem float-index layout
#define XST  132                          // X stride (2-way max conflicts on B frags)
#define WST  68                           // W stride (conflict-free A frags)
#define XS_F 0                            // 64*132 = 8448
#define WS_F 8448                         // 64*68  = 4352
#define AX0  12800                        // pass1: kw[64]   pass2: voff[64]
#define AX1  12864                        // pass2: av[64]   pass1: red[8]
#define AX2  12928                        // pass2: mv[64]
#define AX3  12992                        // pass2: es[128]
#define AX4  13120                        // pass2: red[8]
#define SMT1 ((12880)*4)
#define SMT2 ((13128)*4)

// ---------------- helpers ---------------------------------------------------
__device__ __forceinline__ unsigned ordf(float f) {
    unsigned u = __float_as_uint(f);
    return (u & 0x80000000u) ? ~u : (u | 0x80000000u);
}
__device__ __forceinline__ float deord(unsigned u) {
    u = (u & 0x80000000u) ? (u & 0x7fffffffu) : ~u;
    return __uint_as_float(u);
}
__device__ __forceinline__ float siluf(float z) {
    return __fdividef(z, 1.f + __expf(-z));
}
__device__ __forceinline__ float tf32r(float f) {
    uint32_t r; asm("cvt.rna.tf32.f32 %0, %1;" : "=r"(r) : "f"(f));
    return __uint_as_float(r);
}
#define MMA_TF32(C, a0, a1, a2, a3, b0, b1)                                     \
    asm volatile("mma.sync.aligned.m16n8k8.row.col.f32.tf32.tf32.f32 "          \
        "{%0,%1,%2,%3}, {%4,%5,%6,%7}, {%8,%9}, {%0,%1,%2,%3};"                 \
        : "+f"((C)[0]), "+f"((C)[1]), "+f"((C)[2]), "+f"((C)[3])                \
        : "r"(a0), "r"(a1), "r"(a2), "r"(a3), "r"(b0), "r"(b1))

// ---------------- init: zero accumulators + fold BN + tf32-round weights ----
__global__ void k_init(const float* conv_w,
                       const float* key_w, const float* key_g, const float* key_b,
                       const float* key_m, const float* key_v,
                       const float* val_w, const float* val_g, const float* val_b,
                       const float* val_m, const float* val_v,
                       const float* half_w, const float* half_g, const float* half_b,
                       const float* half_m, const float* half_v) {
    int t = threadIdx.x;
    for (int i = t; i < 2*NB*CCH; i += 256) { g_sumx[i] = 0.f; g_cmax[i] = 0u; g_fea[i] = 0.f; }
    for (int i = t; i < 2*NB; i += 256) { g_kmax[i] = 0u; g_Z[i] = 0.f; }
    for (int i = t; i < 4096; i += 256) {
        int o = i >> 6;
        g_convw_r[i] = tf32r(conv_w[i]);
        float vs = val_g[o] * rsqrtf(val_v[o] + EPSV);
        g_valw_r[i] = tf32r(val_w[i] * vs);
    }
    if (t < CCH) {
        float ks = key_g[0] * rsqrtf(key_v[0] + EPSV);
        g_keywf[t] = key_w[t] * ks;
        float vs = val_g[t] * rsqrtf(val_v[t] + EPSV);
        g_valoff[t] = val_b[t] - val_m[t] * vs;
        if (t == 0) g_sc[0] = key_b[0] - key_m[0] * ks;
        if (t == 1) {
            float hs = half_g[0] * rsqrtf(half_v[0] + EPSV);
            g_sc[1] = half_w[0] * hs;
            g_sc[2] = half_w[1] * hs;
            g_sc[3] = half_b[0] - half_m[0] * hs;
        }
    }
}

// ---------------- pass1: tf32 MMA conv GEMM -> cmax; x sums; key logits -----
__global__ void __launch_bounds__(256, 4)
k_pass1(const float* __restrict__ xr, const float* __restrict__ xi) {
    extern __shared__ float sm[];
    float* Xs  = sm + XS_F;
    float* Ws  = sm + WS_F;
    float* kw  = sm + AX0;
    float* red = sm + AX1;
    int s = blockIdx.z, n = blockIdx.y;
    int p0 = blockIdx.x * TP;
    int t = threadIdx.x, lane = t & 31, w = t >> 5;
    const float* x = (s == 0 ? xr : xi) + (size_t)n * CCH * HW + p0;
    int base = (s*NB + n) * CCH;
    size_t kbase = (size_t)(s*NB + n) * HW + p0;

    // load X (tf32-rounded) + exact raw channel sums folded into load
    #pragma unroll
    for (int m = 0; m < 8; m++) {
        int c = w + 8*m;
        float4 v = *(const float4*)(x + (size_t)c*HW + lane*4);
        float ps = (v.x + v.y) + (v.z + v.w);
        #pragma unroll
        for (int k = 16; k >= 1; k >>= 1) ps += __shfl_xor_sync(0xffffffffu, ps, k);
        if (lane == 0) atomicAdd(&g_sumx[base + c], ps);
        float4 o4;
        o4.x = tf32r(v.x); o4.y = tf32r(v.y); o4.z = tf32r(v.z); o4.w = tf32r(v.w);
        *(float4*)(Xs + c*XST + lane*4) = o4;
    }
    for (int i = t; i < 4096; i += 256) Ws[(i >> 6)*WST + (i & 63)] = g_convw_r[i];
    if (t < 64) kw[t] = g_keywf[t];
    __syncthreads();

    // GEMM: warp = 16 out-ch x 64 px, k-outer, C frags resident
    int gid = lane >> 2, tid4 = lane & 3;
    int o0 = (w & 3) * 16, pb = (w >> 2) * 64;
    float C[8][4];
    #pragma unroll
    for (int nf = 0; nf < 8; nf++) { C[nf][0]=0.f; C[nf][1]=0.f; C[nf][2]=0.f; C[nf][3]=0.f; }
    #pragma unroll
    for (int kk = 0; kk < 8; kk++) {
        const float* wr = Ws + (o0 + gid)*WST + kk*8 + tid4;
        uint32_t a0 = __float_as_uint(wr[0]);
        uint32_t a1 = __float_as_uint(wr[8*WST]);
        uint32_t a2 = __float_as_uint(wr[4]);
        uint32_t a3 = __float_as_uint(wr[8*WST + 4]);
        const float* xb = Xs + (kk*8 + tid4)*XST + pb + gid;
        #pragma unroll
        for (int nf = 0; nf < 8; nf++) {
            uint32_t b0 = __float_as_uint(xb[nf*8]);
            uint32_t b1 = __float_as_uint(xb[nf*8 + 4*XST]);
            MMA_TF32(C[nf], a0, a1, a2, a3, b0, b1);
        }
    }
    // channel max straight from frags (bias added in k_mid)
    float mx0 = -1e30f, mx1 = -1e30f;
    #pragma unroll
    for (int nf = 0; nf < 8; nf++) {
        mx0 = fmaxf(mx0, fmaxf(C[nf][0], C[nf][1]));
        mx1 = fmaxf(mx1, fmaxf(C[nf][2], C[nf][3]));
    }
    mx0 = fmaxf(mx0, __shfl_xor_sync(0xffffffffu, mx0, 1));
    mx0 = fmaxf(mx0, __shfl_xor_sync(0xffffffffu, mx0, 2));
    mx1 = fmaxf(mx1, __shfl_xor_sync(0xffffffffu, mx1, 1));
    mx1 = fmaxf(mx1, __shfl_xor_sync(0xffffffffu, mx1, 2));
    if (tid4 == 0) {
        atomicMax(&g_cmax[base + o0 + gid], ordf(mx0));
        atomicMax(&g_cmax[base + o0 + gid + 8], ordf(mx1));
    }

    // key logit: two threads per pixel, split channel halves
    int p = t >> 1, h = t & 1;
    float z = 0.f;
    #pragma unroll 8
    for (int c = 32*h; c < 32*h + 32; c++) z = fmaf(kw[c], Xs[c*XST + p], z);
    z += __shfl_xor_sync(0xffffffffu, z, 1);
    z += g_sc[0];
    float kl = siluf(z);
    if (h == 0) g_klog[kbase + p] = kl;
    float km = (h == 0) ? kl : -1e30f;
    #pragma unroll
    for (int k = 16; k >= 1; k >>= 1) km = fmaxf(km, __shfl_xor_sync(0xffffffffu, km, k));
    if (lane == 0) red[w] = km;
    __syncthreads();
    if (t == 0) {
        float m = red[0];
        #pragma unroll
        for (int q = 1; q < 8; q++) m = fmaxf(m, red[q]);
        atomicMax(&g_kmax[s*NB + n], ordf(m));
    }
}

// ---------------- mid: channel softmaxes ------------------------------------
__device__ __forceinline__ float blockmax64(float v, float* tmp) {
    tmp[threadIdx.x] = v; __syncthreads();
    for (int k = 32; k >= 1; k >>= 1) {
        if (threadIdx.x < k) tmp[threadIdx.x] = fmaxf(tmp[threadIdx.x], tmp[threadIdx.x + k]);
        __syncthreads();
    }
    float r = tmp[0]; __syncthreads(); return r;
}
__device__ __forceinline__ float blocksum64(float v, float* tmp) {
    tmp[threadIdx.x] = v; __syncthreads();
    for (int k = 32; k >= 1; k >>= 1) {
        if (threadIdx.x < k) tmp[threadIdx.x] += tmp[threadIdx.x + k];
        __syncthreads();
    }
    float r = tmp[0]; __syncthreads(); return r;
}

__global__ void k_mid(const float* __restrict__ conv_w, const float* __restrict__ conv_b) {
    int s = blockIdx.x, n = blockIdx.y, o = threadIdx.x;
    __shared__ float sx[64], tmp[64];
    int base = (s*NB + n) * CCH;
    sx[o] = g_sumx[base + o] * (1.f / (float)HW);
    __syncthreads();
    float mean = conv_b[o];
    for (int c = 0; c < 64; c++) mean = fmaf(sx[c], conv_w[o*64 + c], mean);
    float mx = deord(g_cmax[base + o]) + conv_b[o];

    float m1 = blockmax64(mean, tmp);
    float e1 = expf(mean - m1);
    float s1 = blocksum64(e1, tmp);
    g_avg[base + o] = e1 / s1;

    float m2 = blockmax64(mx, tmp);
    float e2 = expf(mx - m2);
    float s2 = blocksum64(e2, tmp);
    g_msm[base + o] = e2 / s2;
}

// ---------------- pass2: tf32 MMA val GEMM; fused es/Z/fea/half --------------
__global__ void __launch_bounds__(256, 4)
k_pass2(const float* __restrict__ xr, const float* __restrict__ xi) {
    extern __shared__ float sm[];
    float* Xs   = sm + XS_F;   // X, then overwritten with V
    float* Ws   = sm + WS_F;
    float* voff = sm + AX0;
    float* av   = sm + AX1;
    float* mv   = sm + AX2;
    float* es   = sm + AX3;
    float* red  = sm + AX4;
    int sx = blockIdx.z, n = blockIdx.y, so = 1 - sx;   // V of side sx feeds output side so
    int p0 = blockIdx.x * TP;
    int t = threadIdx.x, lane = t & 31, w = t >> 5;
    const float* x = (sx == 0 ? xr : xi) + (size_t)n * CCH * HW + p0;
    int sn2 = so*NB + n;
    int base2 = sn2 * CCH;
    size_t kbase2 = (size_t)sn2 * HW + p0;

    // load X (tf32-rounded)
    #pragma unroll
    for (int m = 0; m < 8; m++) {
        int c = w + 8*m;
        float4 v = *(const float4*)(x + (size_t)c*HW + lane*4);
        float4 o4;
        o4.x = tf32r(v.x); o4.y = tf32r(v.y); o4.z = tf32r(v.z); o4.w = tf32r(v.w);
        *(float4*)(Xs + c*XST + lane*4) = o4;
    }
    for (int i = t; i < 4096; i += 256) Ws[(i >> 6)*WST + (i & 63)] = g_valw_r[i];
    if (t < 64) {
        voff[t] = g_valoff[t];
        av[t]   = g_avg[base2 + t];
        mv[t]   = g_msm[base2 + t];
    }
    // es + Z prologue (independent of the GEMM)
    if (t < 128) {
        float kmaxv = deord(g_kmax[sn2]);
        float e = __expf(g_klog[kbase2 + t] - kmaxv);
        es[t] = e;
        float zp = e;
        #pragma unroll
        for (int k = 16; k >= 1; k >>= 1) zp += __shfl_xor_sync(0xffffffffu, zp, k);
        if (lane == 0) red[w] = zp;
    }
    __syncthreads();
    if (t == 0) atomicAdd(&g_Z[sn2], (red[0] + red[1]) + (red[2] + red[3]));

    // GEMM
    int gid = lane >> 2, tid4 = lane & 3;
    int o0 = (w & 3) * 16, pb = (w >> 2) * 64;
    float C[8][4];
    #pragma unroll
    for (int nf = 0; nf < 8; nf++) { C[nf][0]=0.f; C[nf][1]=0.f; C[nf][2]=0.f; C[nf][3]=0.f; }
    #pragma unroll
    for (int kk = 0; kk < 8; kk++) {
        const float* wr = Ws + (o0 + gid)*WST + kk*8 + tid4;
        uint32_t a0 = __float_as_uint(wr[0]);
        uint32_t a1 = __float_as_uint(wr[8*WST]);
        uint32_t a2 = __float_as_uint(wr[4]);
        uint32_t a3 = __float_as_uint(wr[8*WST + 4]);
        const float* xb = Xs + (kk*8 + tid4)*XST + pb + gid;
        #pragma unroll
        for (int nf = 0; nf < 8; nf++) {
            uint32_t b0 = __float_as_uint(xb[nf*8]);
            uint32_t b1 = __float_as_uint(xb[nf*8 + 4*XST]);
            MMA_TF32(C[nf], a0, a1, a2, a3, b0, b1);
        }
    }
    float off0 = voff[o0 + gid], off1 = voff[o0 + gid + 8];
    __syncthreads();   // all warps done READING Xs before we overwrite with V

    #pragma unroll
    for (int nf = 0; nf < 8; nf++) {
        int pp = pb + nf*8 + 2*tid4;
        float2 u0, u1;
        u0.x = siluf(C[nf][0] + off0); u0.y = siluf(C[nf][1] + off0);
        u1.x = siluf(C[nf][2] + off1); u1.y = siluf(C[nf][3] + off1);
        *(float2*)(Xs + (o0 + gid)*XST + pp) = u0;
        *(float2*)(Xs + (o0 + gid + 8)*XST + pp) = u1;
    }
    __syncthreads();

    // fea[c] = sum_p V[c][p] * e[p]: warp w -> channels 8w..8w+7, lane -> 4 px
    float4 ev = *(const float4*)(es + 4*lane);
    #pragma unroll
    for (int i = 0; i < 8; i++) {
        int c = 8*w + i;
        float4 vv = *(const float4*)(Xs + c*XST + 4*lane);
        float fs = fmaf(vv.x, ev.x, fmaf(vv.y, ev.y, fmaf(vv.z, ev.z, vv.w * ev.w)));
        #pragma unroll
        for (int k = 16; k >= 1; k >>= 1) fs += __shfl_xor_sync(0xffffffffu, fs, k);
        if (lane == 0) atomicAdd(&g_fea[base2 + c], fs);
    }

    // half: two threads per pixel
    int p = t >> 1, h = t & 1;
    float sa = 0.f, smx = 0.f;
    #pragma unroll 8
    for (int c = 32*h; c < 32*h + 32; c++) {
        float vv = Xs[c*XST + p];
        sa  = fmaf(av[c], vv, sa);
        smx = fmaf(mv[c], vv, smx);
    }
    sa  += __shfl_xor_sync(0xffffffffu, sa, 1);
    smx += __shfl_xor_sync(0xffffffffu, smx, 1);
    if (h == 0) {
        float pre = g_sc[1]*sa + g_sc[2]*smx + g_sc[3];
        g_half[kbase2 + p] = siluf(pre);
    }
}

// ---------------- gate: fea/Z -> convb -> LN -> sigmoid --------------------
__global__ void k_gate(const float* __restrict__ convb_w,
                       const float* __restrict__ ln_g, const float* __restrict__ ln_b) {
    int so = blockIdx.x, n = blockIdx.y, o = threadIdx.x;
    __shared__ float ff[64], tmp[64];
    int base = (so*NB + n) * CCH;
    float Z = g_Z[so*NB + n];
    ff[o] = g_fea[base + o] / Z;
    __syncthreads();
    float v = 0.f;
    for (int c = 0; c < 64; c++) v = fmaf(ff[c], convb_w[o*64 + c], v);
    float mu = blocksum64(v, tmp) * (1.f/64.f);
    float d = v - mu;
    float var = blocksum64(d*d, tmp) * (1.f/64.f);
    float gz = d * rsqrtf(var + EPSV) * ln_g[o] + ln_b[o];
    g_gate[base + o] = 1.f / (1.f + expf(-gz));
}

// ---------------- pass3: out = gate*half + me ------------------------------
__global__ void k_pass3(const float* __restrict__ xr, const float* __restrict__ xi,
                        float* __restrict__ out) {
    size_t g = (size_t)blockIdx.x * blockDim.x + threadIdx.x;
    int cl = (int)(g >> 14);
    int p4 = (int)(g & 16383);
    int s = cl >> 9, n = (cl >> 6) & 7, c = cl & 63;
    float gate = g_gate[(s*NB + n)*CCH + c];
    float4 h4 = *(const float4*)(g_half + ((size_t)(s*NB + n) << 16) + (size_t)p4*4);
    const float* x = (s == 0 ? xr : xi);
    float4 m4 = *(const float4*)(x + (((size_t)n*64 + c) << 16) + (size_t)p4*4);
    float4 o4;
    o4.x = fmaf(gate, h4.x, m4.x);
    o4.y = fmaf(gate, h4.y, m4.y);
    o4.z = fmaf(gate, h4.z, m4.z);
    o4.w = fmaf(gate, h4.w, m4.w);
    *(float4*)(out + (g << 2)) = o4;
}

// ---------------- launch ---------------------------------------------------
extern "C" void kernel_launch(void* const* d_in, const int* in_sizes, int n_in,
                              void* d_out, int out_size) {
    const float* rgb    = (const float*)d_in[0];
    const float* ir     = (const float*)d_in[1];
    const float* conv_w = (const float*)d_in[2];
    const float* conv_b = (const float*)d_in[3];
    const float* key_w  = (const float*)d_in[4];
    const float* key_g  = (const float*)d_in[5];
    const float* key_b  = (const float*)d_in[6];
    const float* key_m  = (const float*)d_in[7];
    const float* key_v  = (const float*)d_in[8];
    const float* val_w  = (const float*)d_in[9];
    const float* val_g  = (const float*)d_in[10];
    const float* val_b  = (const float*)d_in[11];
    const float* val_m  = (const float*)d_in[12];
    const float* val_v  = (const float*)d_in[13];
    const float* convb_w= (const float*)d_in[14];
    const float* half_w = (const float*)d_in[15];
    const float* half_g = (const float*)d_in[16];
    const float* half_b = (const float*)d_in[17];
    const float* half_m = (const float*)d_in[18];
    const float* half_v = (const float*)d_in[19];
    const float* ln_g   = (const float*)d_in[20];
    const float* ln_b   = (const float*)d_in[21];
    float* out = (float*)d_out;

    cudaFuncSetAttribute(k_pass1, cudaFuncAttributeMaxDynamicSharedMemorySize, SMT1);
    cudaFuncSetAttribute(k_pass2, cudaFuncAttributeMaxDynamicSharedMemorySize, SMT2);

    k_init<<<1, 256>>>(conv_w, key_w, key_g, key_b, key_m, key_v,
                       val_w, val_g, val_b, val_m, val_v,
                       half_w, half_g, half_b, half_m, half_v);
    dim3 gP(HW / TP, NB, 2);
    k_pass1<<<gP, 256, SMT1>>>(rgb, ir);
    k_mid<<<dim3(2, NB), 64>>>(conv_w, conv_b);
    k_pass2<<<gP, 256, SMT2>>>(rgb, ir);
    k_gate<<<dim3(2, NB), 64>>>(convb_w, ln_g, ln_b);
    k_pass3<<<65536, 256>>>(rgb, ir, out);
}

// round 13
// speedup vs baseline: 1.1837x; 1.1045x over previous
#include <cuda_runtime.h>
#include <math.h>
#include <stdint.h>

#define EPSV 1e-5f
#define HW   65536
#define CCH  64
#define NB   8
#define TP   128

// ---------------- scratch (device globals; no runtime allocation) ----------
__device__ float    g_sumx[2*NB*CCH];
__device__ unsigned g_cmax[2*NB*CCH];
__device__ unsigned g_kmax[2*NB];
__device__ float    g_klog[2*NB*HW];     // 4 MB
__device__ float    g_fea [2*NB*CCH];
__device__ float    g_Z   [2*NB];
__device__ float    g_avg [2*NB*CCH];
__device__ float    g_msm [2*NB*CCH];
__device__ float    g_gate[2*NB*CCH];
__device__ float    g_half[2*NB*HW];     // 4 MB
__device__ __align__(16) float g_convw_r[CCH*CCH];  // conv_w, tf32-rounded [o][k]
__device__ __align__(16) float g_valw_r[CCH*CCH];   // val_w*BNscale, tf32-rounded [o][k]
__device__ float    g_keywf[CCH];
__device__ float    g_valoff[CCH];
__device__ float    g_sc[4];             // keyoff, hw0, hw1, hoff

// smem float-index layout
#define XST  136                          // X stride: B-frag banks 8*tid4+gid -> conflict-free
#define WST  68                           // W stride: A-frag banks 4*gid+tid4 -> conflict-free
#define XS_F 0                            // 64*136 = 8704
#define WS_F 8704                         // 64*68  = 4352
#define AX0  13056                        // pass1: kw[64]   pass2: voff[64]
#define AX1  13120                        // pass1: red[8]   pass2: av[64]
#define AX2  13184                        // pass2: mv[64]
#define AX3  13248                        // pass2: es[128]
#define AX4  13376                        // pass2: red[8]
#define SMT1 ((13128)*4)
#define SMT2 ((13384)*4)

// ---------------- helpers ---------------------------------------------------
__device__ __forceinline__ uint32_t s2u(const void* p) {
    uint32_t a;
    asm("{ .reg .u64 t; cvta.to.shared.u64 t, %1; cvt.u32.u64 %0, t; }" : "=r"(a) : "l"(p));
    return a;
}
__device__ __forceinline__ void cpa16(uint32_t dst, const void* src) {
    asm volatile("cp.async.ca.shared.global [%0], [%1], 16;" :: "r"(dst), "l"(src));
}
__device__ __forceinline__ void cpa_wait() {
    asm volatile("cp.async.commit_group;");
    asm volatile("cp.async.wait_group 0;" ::: "memory");
}
__device__ __forceinline__ unsigned ordf(float f) {
    unsigned u = __float_as_uint(f);
    return (u & 0x80000000u) ? ~u : (u | 0x80000000u);
}
__device__ __forceinline__ float deord(unsigned u) {
    u = (u & 0x80000000u) ? (u & 0x7fffffffu) : ~u;
    return __uint_as_float(u);
}
__device__ __forceinline__ float siluf(float z) {
    return __fdividef(z, 1.f + __expf(-z));
}
__device__ __forceinline__ float tf32r(float f) {
    uint32_t r; asm("cvt.rna.tf32.f32 %0, %1;" : "=r"(r) : "f"(f));
    return __uint_as_float(r);
}
#define MMA_TF32(C, a0, a1, a2, a3, b0, b1)                                     \
    asm volatile("mma.sync.aligned.m16n8k8.row.col.f32.tf32.tf32.f32 "          \
        "{%0,%1,%2,%3}, {%4,%5,%6,%7}, {%8,%9}, {%0,%1,%2,%3};"                 \
        : "+f"((C)[0]), "+f"((C)[1]), "+f"((C)[2]), "+f"((C)[3])                \
        : "r"(a0), "r"(a1), "r"(a2), "r"(a3), "r"(b0), "r"(b1))

// ---------------- init: zero accumulators + fold BN + tf32-round weights ----
__global__ void k_init(const float* conv_w,
                       const float* key_w, const float* key_g, const float* key_b,
                       const float* key_m, const float* key_v,
                       const float* val_w, const float* val_g, const float* val_b,
                       const float* val_m, const float* val_v,
                       const float* half_w, const float* half_g, const float* half_b,
                       const float* half_m, const float* half_v) {
    int t = threadIdx.x;
    for (int i = t; i < 2*NB*CCH; i += 256) { g_sumx[i] = 0.f; g_cmax[i] = 0u; g_fea[i] = 0.f; }
    for (int i = t; i < 2*NB; i += 256) { g_kmax[i] = 0u; g_Z[i] = 0.f; }
    for (int i = t; i < 4096; i += 256) {
        int o = i >> 6;
        g_convw_r[i] = tf32r(conv_w[i]);
        float vs = val_g[o] * rsqrtf(val_v[o] + EPSV);
        g_valw_r[i] = tf32r(val_w[i] * vs);
    }
    if (t < CCH) {
        float ks = key_g[0] * rsqrtf(key_v[0] + EPSV);
        g_keywf[t] = key_w[t] * ks;
        float vs = val_g[t] * rsqrtf(val_v[t] + EPSV);
        g_valoff[t] = val_b[t] - val_m[t] * vs;
        if (t == 0) g_sc[0] = key_b[0] - key_m[0] * ks;
        if (t == 1) {
            float hs = half_g[0] * rsqrtf(half_v[0] + EPSV);
            g_sc[1] = half_w[0] * hs;
            g_sc[2] = half_w[1] * hs;
            g_sc[3] = half_b[0] - half_m[0] * hs;
        }
    }
}

// ---------------- pass1: tf32 MMA conv GEMM -> cmax; x sums; key logits -----
__global__ void __launch_bounds__(256, 4)
k_pass1(const float* __restrict__ xr, const float* __restrict__ xi) {
    extern __shared__ float sm[];
    float* Xs  = sm + XS_F;
    float* Ws  = sm + WS_F;
    float* kw  = sm + AX0;
    float* red = sm + AX1;
    int s = blockIdx.z, n = blockIdx.y;
    int p0 = blockIdx.x * TP;
    int t = threadIdx.x, lane = t & 31, w = t >> 5;
    const float* x = (s == 0 ? xr : xi) + (size_t)n * CCH * HW + p0;
    int base = (s*NB + n) * CCH;
    size_t kbase = (size_t)(s*NB + n) * HW + p0;

    // W via cp.async (overlaps the X LDG loop below)
    uint32_t ws_u = s2u(Ws);
    #pragma unroll
    for (int j = 0; j < 4; j++) {
        int f = t + 256*j;
        cpa16(ws_u + ((f >> 4)*WST + (f & 15)*4)*4, g_convw_r + (f << 2));
    }
    // X raw (no cvt: MMA truncates to tf32 in HW) + exact channel sums
    #pragma unroll
    for (int m = 0; m < 8; m++) {
        int c = w + 8*m;
        float4 v = *(const float4*)(x + (size_t)c*HW + lane*4);
        float ps = (v.x + v.y) + (v.z + v.w);
        #pragma unroll
        for (int k = 16; k >= 1; k >>= 1) ps += __shfl_xor_sync(0xffffffffu, ps, k);
        if (lane == 0) atomicAdd(&g_sumx[base + c], ps);
        *(float4*)(Xs + c*XST + lane*4) = v;
    }
    if (t < 64) kw[t] = g_keywf[t];
    cpa_wait();
    __syncthreads();

    // GEMM: warp = 16 out-ch x 64 px, k-outer, C frags resident
    int gid = lane >> 2, tid4 = lane & 3;
    int o0 = (w & 3) * 16, pb = (w >> 2) * 64;
    float C[8][4];
    #pragma unroll
    for (int nf = 0; nf < 8; nf++) { C[nf][0]=0.f; C[nf][1]=0.f; C[nf][2]=0.f; C[nf][3]=0.f; }
    #pragma unroll
    for (int kk = 0; kk < 8; kk++) {
        const float* wr = Ws + (o0 + gid)*WST + kk*8 + tid4;
        uint32_t a0 = __float_as_uint(wr[0]);
        uint32_t a1 = __float_as_uint(wr[8*WST]);
        uint32_t a2 = __float_as_uint(wr[4]);
        uint32_t a3 = __float_as_uint(wr[8*WST + 4]);
        const float* xb = Xs + (kk*8 + tid4)*XST + pb + gid;
        #pragma unroll
        for (int nf = 0; nf < 8; nf++) {
            uint32_t b0 = __float_as_uint(xb[nf*8]);
            uint32_t b1 = __float_as_uint(xb[nf*8 + 4*XST]);
            MMA_TF32(C[nf], a0, a1, a2, a3, b0, b1);
        }
    }
    // channel max straight from frags (bias added in k_mid)
    float mx0 = -1e30f, mx1 = -1e30f;
    #pragma unroll
    for (int nf = 0; nf < 8; nf++) {
        mx0 = fmaxf(mx0, fmaxf(C[nf][0], C[nf][1]));
        mx1 = fmaxf(mx1, fmaxf(C[nf][2], C[nf][3]));
    }
    mx0 = fmaxf(mx0, __shfl_xor_sync(0xffffffffu, mx0, 1));
    mx0 = fmaxf(mx0, __shfl_xor_sync(0xffffffffu, mx0, 2));
    mx1 = fmaxf(mx1, __shfl_xor_sync(0xffffffffu, mx1, 1));
    mx1 = fmaxf(mx1, __shfl_xor_sync(0xffffffffu, mx1, 2));
    if (tid4 == 0) {
        atomicMax(&g_cmax[base + o0 + gid], ordf(mx0));
        atomicMax(&g_cmax[base + o0 + gid + 8], ordf(mx1));
    }

    // key logit: two threads per pixel, split channel halves (raw X -> exact)
    int p = t >> 1, h = t & 1;
    float z = 0.f;
    #pragma unroll 8
    for (int c = 32*h; c < 32*h + 32; c++) z = fmaf(kw[c], Xs[c*XST + p], z);
    z += __shfl_xor_sync(0xffffffffu, z, 1);
    z += g_sc[0];
    float kl = siluf(z);
    if (h == 0) g_klog[kbase + p] = kl;
    float km = (h == 0) ? kl : -1e30f;
    #pragma unroll
    for (int k = 16; k >= 1; k >>= 1) km = fmaxf(km, __shfl_xor_sync(0xffffffffu, km, k));
    if (lane == 0) red[w] = km;
    __syncthreads();
    if (t == 0) {
        float m = red[0];
        #pragma unroll
        for (int q = 1; q < 8; q++) m = fmaxf(m, red[q]);
        atomicMax(&g_kmax[s*NB + n], ordf(m));
    }
}

// ---------------- mid: channel softmaxes ------------------------------------
__device__ __forceinline__ float blockmax64(float v, float* tmp) {
    tmp[threadIdx.x] = v; __syncthreads();
    for (int k = 32; k >= 1; k >>= 1) {
        if (threadIdx.x < k) tmp[threadIdx.x] = fmaxf(tmp[threadIdx.x], tmp[threadIdx.x + k]);
        __syncthreads();
    }
    float r = tmp[0]; __syncthreads(); return r;
}
__device__ __forceinline__ float blocksum64(float v, float* tmp) {
    tmp[threadIdx.x] = v; __syncthreads();
    for (int k = 32; k >= 1; k >>= 1) {
        if (threadIdx.x < k) tmp[threadIdx.x] += tmp[threadIdx.x + k];
        __syncthreads();
    }
    float r = tmp[0]; __syncthreads(); return r;
}

__global__ void k_mid(const float* __restrict__ conv_w, const float* __restrict__ conv_b) {
    int s = blockIdx.x, n = blockIdx.y, o = threadIdx.x;
    __shared__ float sx[64], tmp[64];
    int base = (s*NB + n) * CCH;
    sx[o] = g_sumx[base + o] * (1.f / (float)HW);
    __syncthreads();
    float mean = conv_b[o];
    for (int c = 0; c < 64; c++) mean = fmaf(sx[c], conv_w[o*64 + c], mean);
    float mx = deord(g_cmax[base + o]) + conv_b[o];

    float m1 = blockmax64(mean, tmp);
    float e1 = expf(mean - m1);
    float s1 = blocksum64(e1, tmp);
    g_avg[base + o] = e1 / s1;

    float m2 = blockmax64(mx, tmp);
    float e2 = expf(mx - m2);
    float s2 = blocksum64(e2, tmp);
    g_msm[base + o] = e2 / s2;
}

// ---------------- pass2: tf32 MMA val GEMM; fused es/Z/fea/half --------------
__global__ void __launch_bounds__(256, 4)
k_pass2(const float* __restrict__ xr, const float* __restrict__ xi) {
    extern __shared__ float sm[];
    float* Xs   = sm + XS_F;   // X, then overwritten with V
    float* Ws   = sm + WS_F;
    float* voff = sm + AX0;
    float* av   = sm + AX1;
    float* mv   = sm + AX2;
    float* es   = sm + AX3;
    float* red  = sm + AX4;
    int sx = blockIdx.z, n = blockIdx.y, so = 1 - sx;   // V of side sx feeds output side so
    int p0 = blockIdx.x * TP;
    int t = threadIdx.x, lane = t & 31, w = t >> 5;
    const float* x = (sx == 0 ? xr : xi) + (size_t)n * CCH * HW + p0;
    int sn2 = so*NB + n;
    int base2 = sn2 * CCH;
    size_t kbase2 = (size_t)sn2 * HW + p0;

    // X + W via cp.async (raw f32; MMA truncates to tf32)
    uint32_t xs_u = s2u(Xs), ws_u = s2u(Ws);
    #pragma unroll
    for (int m = 0; m < 8; m++) {
        int c = w + 8*m;
        cpa16(xs_u + (c*XST + lane*4)*4, x + (size_t)c*HW + lane*4);
    }
    #pragma unroll
    for (int j = 0; j < 4; j++) {
        int f = t + 256*j;
        cpa16(ws_u + ((f >> 4)*WST + (f & 15)*4)*4, g_valw_r + (f << 2));
    }
    if (t < 64) {
        voff[t] = g_valoff[t];
        av[t]   = g_avg[base2 + t];
        mv[t]   = g_msm[base2 + t];
    }
    // es + Z partials (overlaps cp.async)
    if (t < 128) {
        float kmaxv = deord(g_kmax[sn2]);
        float e = __expf(g_klog[kbase2 + t] - kmaxv);
        es[t] = e;
        float zp = e;
        #pragma unroll
        for (int k = 16; k >= 1; k >>= 1) zp += __shfl_xor_sync(0xffffffffu, zp, k);
        if (lane == 0) red[w] = zp;
    }
    cpa_wait();
    __syncthreads();

    // GEMM
    int gid = lane >> 2, tid4 = lane & 3;
    int o0 = (w & 3) * 16, pb = (w >> 2) * 64;
    float C[8][4];
    #pragma unroll
    for (int nf = 0; nf < 8; nf++) { C[nf][0]=0.f; C[nf][1]=0.f; C[nf][2]=0.f; C[nf][3]=0.f; }
    #pragma unroll
    for (int kk = 0; kk < 8; kk++) {
        const float* wr = Ws + (o0 + gid)*WST + kk*8 + tid4;
        uint32_t a0 = __float_as_uint(wr[0]);
        uint32_t a1 = __float_as_uint(wr[8*WST]);
        uint32_t a2 = __float_as_uint(wr[4]);
        uint32_t a3 = __float_as_uint(wr[8*WST + 4]);
        const float* xb = Xs + (kk*8 + tid4)*XST + pb + gid;
        #pragma unroll
        for (int nf = 0; nf < 8; nf++) {
            uint32_t b0 = __float_as_uint(xb[nf*8]);
            uint32_t b1 = __float_as_uint(xb[nf*8 + 4*XST]);
            MMA_TF32(C[nf], a0, a1, a2, a3, b0, b1);
        }
    }
    float off0 = voff[o0 + gid], off1 = voff[o0 + gid + 8];
    __syncthreads();   // all warps done READING Xs before we overwrite with V
    if (t == 0) atomicAdd(&g_Z[sn2], (red[0] + red[1]) + (red[2] + red[3]));

    #pragma unroll
    for (int nf = 0; nf < 8; nf++) {
        int pp = pb + nf*8 + 2*tid4;
        float2 u0, u1;
        u0.x = siluf(C[nf][0] + off0); u0.y = siluf(C[nf][1] + off0);
        u1.x = siluf(C[nf][2] + off1); u1.y = siluf(C[nf][3] + off1);
        *(float2*)(Xs + (o0 + gid)*XST + pp) = u0;
        *(float2*)(Xs + (o0 + gid + 8)*XST + pp) = u1;
    }
    __syncthreads();

    // fea[c] = sum_p V[c][p] * e[p]: warp w -> channels 8w..8w+7, lane -> 4 px
    float4 ev = *(const float4*)(es + 4*lane);
    #pragma unroll
    for (int i = 0; i < 8; i++) {
        int c = 8*w + i;
        float4 vv = *(const float4*)(Xs + c*XST + 4*lane);
        float fs = fmaf(vv.x, ev.x, fmaf(vv.y, ev.y, fmaf(vv.z, ev.z, vv.w * ev.w)));
        #pragma unroll
        for (int k = 16; k >= 1; k >>= 1) fs += __shfl_xor_sync(0xffffffffu, fs, k);
        if (lane == 0) atomicAdd(&g_fea[base2 + c], fs);
    }

    // half: two threads per pixel
    int p = t >> 1, h = t & 1;
    float sa = 0.f, smx = 0.f;
    #pragma unroll 8
    for (int c = 32*h; c < 32*h + 32; c++) {
        float vv = Xs[c*XST + p];
        sa  = fmaf(av[c], vv, sa);
        smx = fmaf(mv[c], vv, smx);
    }
    sa  += __shfl_xor_sync(0xffffffffu, sa, 1);
    smx += __shfl_xor_sync(0xffffffffu, smx, 1);
    if (h == 0) {
        float pre = g_sc[1]*sa + g_sc[2]*smx + g_sc[3];
        g_half[kbase2 + p] = siluf(pre);
    }
}

// ---------------- gate: fea/Z -> convb -> LN -> sigmoid --------------------
__global__ void k_gate(const float* __restrict__ convb_w,
                       const float* __restrict__ ln_g, const float* __restrict__ ln_b) {
    int so = blockIdx.x, n = blockIdx.y, o = threadIdx.x;
    __shared__ float ff[64], tmp[64];
    int base = (so*NB + n) * CCH;
    float Z = g_Z[so*NB + n];
    ff[o] = g_fea[base + o] / Z;
    __syncthreads();
    float v = 0.f;
    for (int c = 0; c < 64; c++) v = fmaf(ff[c], convb_w[o*64 + c], v);
    float mu = blocksum64(v, tmp) * (1.f/64.f);
    float d = v - mu;
    float var = blocksum64(d*d, tmp) * (1.f/64.f);
    float gz = d * rsqrtf(var + EPSV) * ln_g[o] + ln_b[o];
    g_gate[base + o] = 1.f / (1.f + expf(-gz));
}

// ---------------- pass3: out = gate*half + me ------------------------------
__global__ void k_pass3(const float* __restrict__ xr, const float* __restrict__ xi,
                        float* __restrict__ out) {
    size_t g = (size_t)blockIdx.x * blockDim.x + threadIdx.x;
    int cl = (int)(g >> 14);
    int p4 = (int)(g & 16383);
    int s = cl >> 9, n = (cl >> 6) & 7, c = cl & 63;
    float gate = g_gate[(s*NB + n)*CCH + c];
    float4 h4 = *(const float4*)(g_half + ((size_t)(s*NB + n) << 16) + (size_t)p4*4);
    const float* x = (s == 0 ? xr : xi);
    float4 m4 = *(const float4*)(x + (((size_t)n*64 + c) << 16) + (size_t)p4*4);
    float4 o4;
    o4.x = fmaf(gate, h4.x, m4.x);
    o4.y = fmaf(gate, h4.y, m4.y);
    o4.z = fmaf(gate, h4.z, m4.z);
    o4.w = fmaf(gate, h4.w, m4.w);
    *(float4*)(out + (g << 2)) = o4;
}

// ---------------- launch ---------------------------------------------------
extern "C" void kernel_launch(void* const* d_in, const int* in_sizes, int n_in,
                              void* d_out, int out_size) {
    const float* rgb    = (const float*)d_in[0];
    const float* ir     = (const float*)d_in[1];
    const float* conv_w = (const float*)d_in[2];
    const float* conv_b = (const float*)d_in[3];
    const float* key_w  = (const float*)d_in[4];
    const float* key_g  = (const float*)d_in[5];
    const float* key_b  = (const float*)d_in[6];
    const float* key_m  = (const float*)d_in[7];
    const float* key_v  = (const float*)d_in[8];
    const float* val_w  = (const float*)d_in[9];
    const float* val_g  = (const float*)d_in[10];
    const float* val_b  = (const float*)d_in[11];
    const float* val_m  = (const float*)d_in[12];
    const float* val_v  = (const float*)d_in[13];
    const float* convb_w= (const float*)d_in[14];
    const float* half_w = (const float*)d_in[15];
    const float* half_g = (const float*)d_in[16];
    const float* half_b = (const float*)d_in[17];
    const float* half_m = (const float*)d_in[18];
    const float* half_v = (const float*)d_in[19];
    const float* ln_g   = (const float*)d_in[20];
    const float* ln_b   = (const float*)d_in[21];
    float* out = (float*)d_out;

    cudaFuncSetAttribute(k_pass1, cudaFuncAttributeMaxDynamicSharedMemorySize, SMT1);
    cudaFuncSetAttribute(k_pass2, cudaFuncAttributeMaxDynamicSharedMemorySize, SMT2);

    k_init<<<1, 256>>>(conv_w, key_w, key_g, key_b, key_m, key_v,
                       val_w, val_g, val_b, val_m, val_v,
                       half_w, half_g, half_b, half_m, half_v);
    dim3 gP(HW / TP, NB, 2);
    k_pass1<<<gP, 256, SMT1>>>(rgb, ir);
    k_mid<<<dim3(2, NB), 64>>>(conv_w, conv_b);
    k_pass2<<<gP, 256, SMT2>>>(rgb, ir);
    k_gate<<<dim3(2, NB), 64>>>(convb_w, ln_g, ln_b);
    k_pass3<<<65536, 256>>>(rgb, ir, out);
}

// round 14
// speedup vs baseline: 1.2148x; 1.0263x over previous
#include <cuda_runtime.h>
#include <cuda_fp16.h>
#include <math.h>
#include <stdint.h>

#define EPSV 1e-5f
#define HW   65536
#define CCH  64
#define NB   8
#define TP   128

// ---------------- scratch (device globals; no runtime allocation) ----------
__device__ float    g_sumx[2*NB*CCH];
__device__ unsigned g_cmax[2*NB*CCH];
__device__ unsigned g_kmax[2*NB];
__device__ float    g_klog[2*NB*HW];     // 4 MB
__device__ float    g_fea [2*NB*CCH];
__device__ float    g_Z   [2*NB];
__device__ float    g_avg [2*NB*CCH];
__device__ float    g_msm [2*NB*CCH];
__device__ float    g_gate[2*NB*CCH];
__device__ float    g_half[2*NB*HW];     // 4 MB
__device__ __align__(16) __half g_V[(size_t)2*NB*CCH*HW];  // 134 MB fp16 V
__device__ __align__(16) float g_convw_r[CCH*CCH];  // conv_w, tf32-rounded [o][k]
__device__ __align__(16) float g_valw_r[CCH*CCH];   // val_w*BNscale, tf32-rounded [o][k]
__device__ float    g_keywf[CCH];
__device__ float    g_valoff[CCH];
__device__ float    g_sc[4];             // keyoff, hw0, hw1, hoff

// kA smem float-index layout
#define XST  136
#define WST  68
#define W1F  8704      // 64*136 = 8704 for X
#define W2F  13056     // +4352
#define KWF  17408
#define VOF  17472
#define REDF 17536
#define SMTA ((17544)*4)
// kB smem float-index layout (V fp16 rows: 136 half-units = 272 B)
#define QF   4352      // after Vb (64*272 B = 17408 B = 4352 floats)
#define ESF2 4416
#define SMTB ((4544)*4)

// ---------------- helpers ---------------------------------------------------
__device__ __forceinline__ uint32_t s2u(const void* p) {
    uint32_t a;
    asm("{ .reg .u64 t; cvta.to.shared.u64 t, %1; cvt.u32.u64 %0, t; }" : "=r"(a) : "l"(p));
    return a;
}
__device__ __forceinline__ void cpa16(uint32_t dst, const void* src) {
    asm volatile("cp.async.ca.shared.global [%0], [%1], 16;" :: "r"(dst), "l"(src));
}
__device__ __forceinline__ void cpa_wait() {
    asm volatile("cp.async.commit_group;");
    asm volatile("cp.async.wait_group 0;" ::: "memory");
}
__device__ __forceinline__ unsigned ordf(float f) {
    unsigned u = __float_as_uint(f);
    return (u & 0x80000000u) ? ~u : (u | 0x80000000u);
}
__device__ __forceinline__ float deord(unsigned u) {
    u = (u & 0x80000000u) ? (u & 0x7fffffffu) : ~u;
    return __uint_as_float(u);
}
__device__ __forceinline__ float siluf(float z) {
    return __fdividef(z, 1.f + __expf(-z));
}
__device__ __forceinline__ float tf32r(float f) {
    uint32_t r; asm("cvt.rna.tf32.f32 %0, %1;" : "=r"(r) : "f"(f));
    return __uint_as_float(r);
}
#define MMA_TF32(C, a0, a1, a2, a3, b0, b1)                                     \
    asm volatile("mma.sync.aligned.m16n8k8.row.col.f32.tf32.tf32.f32 "          \
        "{%0,%1,%2,%3}, {%4,%5,%6,%7}, {%8,%9}, {%0,%1,%2,%3};"                 \
        : "+f"((C)[0]), "+f"((C)[1]), "+f"((C)[2]), "+f"((C)[3])                \
        : "r"(a0), "r"(a1), "r"(a2), "r"(a3), "r"(b0), "r"(b1))

// ---------------- init: zero accumulators + fold BN + tf32-round weights ----
__global__ void k_init(const float* conv_w,
                       const float* key_w, const float* key_g, const float* key_b,
                       const float* key_m, const float* key_v,
                       const float* val_w, const float* val_g, const float* val_b,
                       const float* val_m, const float* val_v,
                       const float* half_w, const float* half_g, const float* half_b,
                       const float* half_m, const float* half_v) {
    int t = threadIdx.x;
    for (int i = t; i < 2*NB*CCH; i += 256) { g_sumx[i] = 0.f; g_cmax[i] = 0u; g_fea[i] = 0.f; }
    for (int i = t; i < 2*NB; i += 256) { g_kmax[i] = 0u; g_Z[i] = 0.f; }
    for (int i = t; i < 4096; i += 256) {
        int o = i >> 6;
        g_convw_r[i] = tf32r(conv_w[i]);
        float vs = val_g[o] * rsqrtf(val_v[o] + EPSV);
        g_valw_r[i] = tf32r(val_w[i] * vs);
    }
    if (t < CCH) {
        float ks = key_g[0] * rsqrtf(key_v[0] + EPSV);
        g_keywf[t] = key_w[t] * ks;
        float vs = val_g[t] * rsqrtf(val_v[t] + EPSV);
        g_valoff[t] = val_b[t] - val_m[t] * vs;
        if (t == 0) g_sc[0] = key_b[0] - key_m[0] * ks;
        if (t == 1) {
            float hs = half_g[0] * rsqrtf(half_v[0] + EPSV);
            g_sc[1] = half_w[0] * hs;
            g_sc[2] = half_w[1] * hs;
            g_sc[3] = half_b[0] - half_m[0] * hs;
        }
    }
}

// ---------------- kA: one X read -> conv GEMM (cmax) + keylogit + val GEMM (V fp16)
__global__ void __launch_bounds__(256, 3)
kA(const float* __restrict__ xr, const float* __restrict__ xi) {
    extern __shared__ float sm[];
    float* Xs  = sm;
    float* W1  = sm + W1F;
    float* W2  = sm + W2F;
    float* kw  = sm + KWF;
    float* vo  = sm + VOF;
    float* red = sm + REDF;
    __half* VS = (__half*)sm;          // overlays Xs after GEMMs (17408 B < 34816 B)
    int s = blockIdx.z, n = blockIdx.y;
    int p0 = blockIdx.x * TP;
    int t = threadIdx.x, lane = t & 31, w = t >> 5;
    const float* x = (s == 0 ? xr : xi) + (size_t)n * CCH * HW + p0;
    int base = (s*NB + n) * CCH;
    size_t kbase = (size_t)(s*NB + n) * HW + p0;

    // W1+W2 via cp.async (overlap the X LDG loop)
    uint32_t w1u = s2u(W1), w2u = s2u(W2);
    #pragma unroll
    for (int j = 0; j < 4; j++) {
        int f = t + 256*j;
        uint32_t off = ((f >> 4)*WST + (f & 15)*4) * 4;
        cpa16(w1u + off, g_convw_r + (f << 2));
        cpa16(w2u + off, g_valw_r  + (f << 2));
    }
    // X raw LDG + exact channel sums + STS
    #pragma unroll
    for (int m = 0; m < 8; m++) {
        int c = w + 8*m;
        float4 v = *(const float4*)(x + (size_t)c*HW + lane*4);
        float ps = (v.x + v.y) + (v.z + v.w);
        #pragma unroll
        for (int k = 16; k >= 1; k >>= 1) ps += __shfl_xor_sync(0xffffffffu, ps, k);
        if (lane == 0) atomicAdd(&g_sumx[base + c], ps);
        *(float4*)(Xs + c*XST + lane*4) = v;
    }
    if (t < 64) { kw[t] = g_keywf[t]; vo[t] = g_valoff[t]; }
    cpa_wait();
    __syncthreads();

    int gid = lane >> 2, tid4 = lane & 3;
    int o0 = (w & 3) * 16, pb = (w >> 2) * 64;

    // ---- GEMM1: conv ----
    float C[8][4];
    #pragma unroll
    for (int nf = 0; nf < 8; nf++) { C[nf][0]=0.f; C[nf][1]=0.f; C[nf][2]=0.f; C[nf][3]=0.f; }
    #pragma unroll
    for (int kk = 0; kk < 8; kk++) {
        const float* wr = W1 + (o0 + gid)*WST + kk*8 + tid4;
        uint32_t a0 = __float_as_uint(wr[0]);
        uint32_t a1 = __float_as_uint(wr[8*WST]);
        uint32_t a2 = __float_as_uint(wr[4]);
        uint32_t a3 = __float_as_uint(wr[8*WST + 4]);
        const float* xb = Xs + (kk*8 + tid4)*XST + pb + gid;
        #pragma unroll
        for (int nf = 0; nf < 8; nf++) {
            uint32_t b0 = __float_as_uint(xb[nf*8]);
            uint32_t b1 = __float_as_uint(xb[nf*8 + 4*XST]);
            MMA_TF32(C[nf], a0, a1, a2, a3, b0, b1);
        }
    }
    // channel max from frags (bias added in k_mid)
    {
        float mx0 = -1e30f, mx1 = -1e30f;
        #pragma unroll
        for (int nf = 0; nf < 8; nf++) {
            mx0 = fmaxf(mx0, fmaxf(C[nf][0], C[nf][1]));
            mx1 = fmaxf(mx1, fmaxf(C[nf][2], C[nf][3]));
        }
        mx0 = fmaxf(mx0, __shfl_xor_sync(0xffffffffu, mx0, 1));
        mx0 = fmaxf(mx0, __shfl_xor_sync(0xffffffffu, mx0, 2));
        mx1 = fmaxf(mx1, __shfl_xor_sync(0xffffffffu, mx1, 1));
        mx1 = fmaxf(mx1, __shfl_xor_sync(0xffffffffu, mx1, 2));
        if (tid4 == 0) {
            atomicMax(&g_cmax[base + o0 + gid], ordf(mx0));
            atomicMax(&g_cmax[base + o0 + gid + 8], ordf(mx1));
        }
    }

    // ---- GEMM2: val (reuse Xs) ----
    #pragma unroll
    for (int nf = 0; nf < 8; nf++) { C[nf][0]=0.f; C[nf][1]=0.f; C[nf][2]=0.f; C[nf][3]=0.f; }
    #pragma unroll
    for (int kk = 0; kk < 8; kk++) {
        const float* wr = W2 + (o0 + gid)*WST + kk*8 + tid4;
        uint32_t a0 = __float_as_uint(wr[0]);
        uint32_t a1 = __float_as_uint(wr[8*WST]);
        uint32_t a2 = __float_as_uint(wr[4]);
        uint32_t a3 = __float_as_uint(wr[8*WST + 4]);
        const float* xb = Xs + (kk*8 + tid4)*XST + pb + gid;
        #pragma unroll
        for (int nf = 0; nf < 8; nf++) {
            uint32_t b0 = __float_as_uint(xb[nf*8]);
            uint32_t b1 = __float_as_uint(xb[nf*8 + 4*XST]);
            MMA_TF32(C[nf], a0, a1, a2, a3, b0, b1);
        }
    }
    float off0 = vo[o0 + gid], off1 = vo[o0 + gid + 8];

    // key logit: two threads per pixel (raw X -> exact); reads Xs
    {
        int p = t >> 1, h = t & 1;
        float z = 0.f;
        #pragma unroll 8
        for (int c = 32*h; c < 32*h + 32; c++) z = fmaf(kw[c], Xs[c*XST + p], z);
        z += __shfl_xor_sync(0xffffffffu, z, 1);
        z += g_sc[0];
        float kl = siluf(z);
        if (h == 0) g_klog[kbase + p] = kl;
        float km = (h == 0) ? kl : -1e30f;
        #pragma unroll
        for (int k = 16; k >= 1; k >>= 1) km = fmaxf(km, __shfl_xor_sync(0xffffffffu, km, k));
        if (lane == 0) red[w] = km;
    }
    __syncthreads();   // Xs reads done; red ready
    if (t == 0) {
        float m = red[0];
        #pragma unroll
        for (int q = 1; q < 8; q++) m = fmaxf(m, red[q]);
        atomicMax(&g_kmax[s*NB + n], ordf(m));
    }
    // silu + fp16 pack into VS (stride 136 half units = 272 B rows, bank 4g+t)
    #pragma unroll
    for (int nf = 0; nf < 8; nf++) {
        int pp = pb + nf*8 + 2*tid4;
        __half2 h0 = __floats2half2_rn(siluf(C[nf][0] + off0), siluf(C[nf][1] + off0));
        __half2 h1 = __floats2half2_rn(siluf(C[nf][2] + off1), siluf(C[nf][3] + off1));
        *(__half2*)(VS + (o0 + gid)*136 + pp)     = h0;
        *(__half2*)(VS + (o0 + gid + 8)*136 + pp) = h1;
    }
    __syncthreads();
    // coalesced V write
    __half* gv = g_V + (size_t)((s*NB + n) * CCH) * HW + p0;
    #pragma unroll
    for (int i = t; i < 2048; i += 256) {
        int c = i >> 5, u = i & 31;
        uint2 d = *(uint2*)(VS + c*136 + u*4);
        *(uint2*)(gv + (size_t)c*HW + u*4) = d;
    }
}

// ---------------- mid: channel softmaxes ------------------------------------
__device__ __forceinline__ float blockmax64(float v, float* tmp) {
    tmp[threadIdx.x] = v; __syncthreads();
    for (int k = 32; k >= 1; k >>= 1) {
        if (threadIdx.x < k) tmp[threadIdx.x] = fmaxf(tmp[threadIdx.x], tmp[threadIdx.x + k]);
        __syncthreads();
    }
    float r = tmp[0]; __syncthreads(); return r;
}
__device__ __forceinline__ float blocksum64(float v, float* tmp) {
    tmp[threadIdx.x] = v; __syncthreads();
    for (int k = 32; k >= 1; k >>= 1) {
        if (threadIdx.x < k) tmp[threadIdx.x] += tmp[threadIdx.x + k];
        __syncthreads();
    }
    float r = tmp[0]; __syncthreads(); return r;
}

__global__ void k_mid(const float* __restrict__ conv_w, const float* __restrict__ conv_b) {
    int s = blockIdx.x, n = blockIdx.y, o = threadIdx.x;
    __shared__ float sx[64], tmp[64];
    int base = (s*NB + n) * CCH;
    sx[o] = g_sumx[base + o] * (1.f / (float)HW);
    __syncthreads();
    float mean = conv_b[o];
    for (int c = 0; c < 64; c++) mean = fmaf(sx[c], conv_w[o*64 + c], mean);
    float mx = deord(g_cmax[base + o]) + conv_b[o];

    float m1 = blockmax64(mean, tmp);
    float e1 = expf(mean - m1);
    float s1 = blocksum64(e1, tmp);
    g_avg[base + o] = e1 / s1;

    float m2 = blockmax64(mx, tmp);
    float e2 = expf(mx - m2);
    float s2 = blocksum64(e2, tmp);
    g_msm[base + o] = e2 / s2;
}

// ---------------- kB: thin epilogue — es/Z/fea/half from fp16 V --------------
__global__ void __launch_bounds__(256)
kB() {
    extern __shared__ float sm[];
    __half* Vb = (__half*)sm;
    float* q  = sm + QF;
    float* es = sm + ESF2;
    int so = blockIdx.z, n = blockIdx.y, sx = 1 - so;
    int p0 = blockIdx.x * TP;
    int t = threadIdx.x, lane = t & 31, w = t >> 5;
    int sn2 = so*NB + n;
    int base2 = sn2 * CCH;
    size_t kbase2 = (size_t)sn2 * HW + p0;
    const __half* gv = g_V + (size_t)((sx*NB + n) * CCH) * HW + p0;

    uint32_t vbu = s2u(Vb);
    #pragma unroll
    for (int j = 0; j < 4; j++) {
        int f = t + 256*j;
        int c = f >> 4, k = f & 15;
        cpa16(vbu + (uint32_t)(c*272 + k*16), gv + (size_t)c*HW + k*8);
    }
    if (t < 64) q[t] = g_sc[1]*g_avg[base2 + t] + g_sc[2]*g_msm[base2 + t];
    if (t < 128) {
        float e = __expf(g_klog[kbase2 + t] - deord(g_kmax[sn2]));
        es[t] = e;
        float zp = e;
        #pragma unroll
        for (int k = 16; k >= 1; k >>= 1) zp += __shfl_xor_sync(0xffffffffu, zp, k);
        if (lane == 0) atomicAdd(&g_Z[sn2], zp);
    }
    cpa_wait();
    __syncthreads();

    // fea[c] = sum_p V[c][p] e[p]: warp w -> ch {w+8i}, lane -> px 2lane(+1), +64
    float2 e0 = *(const float2*)(es + 2*lane);
    float2 e1 = *(const float2*)(es + 64 + 2*lane);
    #pragma unroll
    for (int i = 0; i < 8; i++) {
        int c = w + 8*i;
        float2 v0 = __half22float2(*(const __half2*)(Vb + c*136 + 2*lane));
        float2 v1 = __half22float2(*(const __half2*)(Vb + c*136 + 64 + 2*lane));
        float fs = fmaf(v0.x, e0.x, fmaf(v0.y, e0.y, fmaf(v1.x, e1.x, v1.y * e1.y)));
        #pragma unroll
        for (int k = 16; k >= 1; k >>= 1) fs += __shfl_xor_sync(0xffffffffu, fs, k);
        if (lane == 0) atomicAdd(&g_fea[base2 + c], fs);
    }

    // half: thread (pq = t>>2 px-pair, h = t&3 ch-quarter, strided ch = h+4i)
    int pq = t >> 2, h = t & 3;
    float sa0 = 0.f, sa1 = 0.f;
    #pragma unroll 8
    for (int i = 0; i < 16; i++) {
        int c = h + 4*i;
        float2 vf = __half22float2(*(const __half2*)(Vb + c*136 + 2*pq));
        float qc = q[c];
        sa0 = fmaf(qc, vf.x, sa0);
        sa1 = fmaf(qc, vf.y, sa1);
    }
    sa0 += __shfl_xor_sync(0xffffffffu, sa0, 1);
    sa0 += __shfl_xor_sync(0xffffffffu, sa0, 2);
    sa1 += __shfl_xor_sync(0xffffffffu, sa1, 1);
    sa1 += __shfl_xor_sync(0xffffffffu, sa1, 2);
    if (h == 0) {
        float2 hh;
        hh.x = siluf(sa0 + g_sc[3]);
        hh.y = siluf(sa1 + g_sc[3]);
        *(float2*)(&g_half[kbase2 + 2*pq]) = hh;
    }
}

// ---------------- gate: fea/Z -> convb -> LN -> sigmoid --------------------
__global__ void k_gate(const float* __restrict__ convb_w,
                       const float* __restrict__ ln_g, const float* __restrict__ ln_b) {
    int so = blockIdx.x, n = blockIdx.y, o = threadIdx.x;
    __shared__ float ff[64], tmp[64];
    int base = (so*NB + n) * CCH;
    float Z = g_Z[so*NB + n];
    ff[o] = g_fea[base + o] / Z;
    __syncthreads();
    float v = 0.f;
    for (int c = 0; c < 64; c++) v = fmaf(ff[c], convb_w[o*64 + c], v);
    float mu = blocksum64(v, tmp) * (1.f/64.f);
    float d = v - mu;
    float var = blocksum64(d*d, tmp) * (1.f/64.f);
    float gz = d * rsqrtf(var + EPSV) * ln_g[o] + ln_b[o];
    g_gate[base + o] = 1.f / (1.f + expf(-gz));
}

// ---------------- pass3: out = gate*half + me ------------------------------
__global__ void k_pass3(const float* __restrict__ xr, const float* __restrict__ xi,
                        float* __restrict__ out) {
    size_t g = (size_t)blockIdx.x * blockDim.x + threadIdx.x;
    int cl = (int)(g >> 14);
    int p4 = (int)(g & 16383);
    int s = cl >> 9, n = (cl >> 6) & 7, c = cl & 63;
    float gate = g_gate[(s*NB + n)*CCH + c];
    float4 h4 = *(const float4*)(g_half + ((size_t)(s*NB + n) << 16) + (size_t)p4*4);
    const float* x = (s == 0 ? xr : xi);
    float4 m4 = *(const float4*)(x + (((size_t)n*64 + c) << 16) + (size_t)p4*4);
    float4 o4;
    o4.x = fmaf(gate, h4.x, m4.x);
    o4.y = fmaf(gate, h4.y, m4.y);
    o4.z = fmaf(gate, h4.z, m4.z);
    o4.w = fmaf(gate, h4.w, m4.w);
    *(float4*)(out + (g << 2)) = o4;
}

// ---------------- launch ---------------------------------------------------
extern "C" void kernel_launch(void* const* d_in, const int* in_sizes, int n_in,
                              void* d_out, int out_size) {
    const float* rgb    = (const float*)d_in[0];
    const float* ir     = (const float*)d_in[1];
    const float* conv_w = (const float*)d_in[2];
    const float* conv_b = (const float*)d_in[3];
    const float* key_w  = (const float*)d_in[4];
    const float* key_g  = (const float*)d_in[5];
    const float* key_b  = (const float*)d_in[6];
    const float* key_m  = (const float*)d_in[7];
    const float* key_v  = (const float*)d_in[8];
    const float* val_w  = (const float*)d_in[9];
    const float* val_g  = (const float*)d_in[10];
    const float* val_b  = (const float*)d_in[11];
    const float* val_m  = (const float*)d_in[12];
    const float* val_v  = (const float*)d_in[13];
    const float* convb_w= (const float*)d_in[14];
    const float* half_w = (const float*)d_in[15];
    const float* half_g = (const float*)d_in[16];
    const float* half_b = (const float*)d_in[17];
    const float* half_m = (const float*)d_in[18];
    const float* half_v = (const float*)d_in[19];
    const float* ln_g   = (const float*)d_in[20];
    const float* ln_b   = (const float*)d_in[21];
    float* out = (float*)d_out;

    cudaFuncSetAttribute(kA, cudaFuncAttributeMaxDynamicSharedMemorySize, SMTA);

    k_init<<<1, 256>>>(conv_w, key_w, key_g, key_b, key_m, key_v,
                       val_w, val_g, val_b, val_m, val_v,
                       half_w, half_g, half_b, half_m, half_v);
    dim3 gP(HW / TP, NB, 2);
    kA<<<gP, 256, SMTA>>>(rgb, ir);
    k_mid<<<dim3(2, NB), 64>>>(conv_w, conv_b);
    kB<<<gP, 256, SMTB>>>();
    k_gate<<<dim3(2, NB), 64>>>(convb_w, ln_g, ln_b);
    k_pass3<<<65536, 256>>>(rgb, ir, out);
}

// round 16
// speedup vs baseline: 1.8856x; 1.5521x over previous
#include <cuda_runtime.h>
#include <cuda_fp16.h>
#include <math.h>
#include <stdint.h>

#define EPSV 1e-5f
#define HW   65536
#define CCH  64
#define NB   8
#define TP   128

// ---------------- scratch (device globals; no runtime allocation) ----------
__device__ float    g_sumx[2*NB*CCH];
__device__ unsigned g_cmax[2*NB*CCH];
__device__ float    g_fea [2*NB*CCH];
__device__ float    g_Z   [2*NB];
__device__ float    g_avg [2*NB*CCH];
__device__ float    g_msm [2*NB*CCH];
__device__ float    g_gate[2*NB*CCH];
__device__ __align__(16) __half g_V[(size_t)2*NB*CCH*HW];  // 134 MB fp16 V
__device__ __align__(16) float g_convw_r[CCH*CCH];  // conv_w, tf32-rounded [o][k]
__device__ __align__(16) float g_valw_r[CCH*CCH];   // val_w*BNscale, tf32-rounded [o][k]
__device__ float    g_keywf[CCH];
__device__ float    g_valoff[CCH];
__device__ float    g_sc[4];             // keyoff, hw0, hw1, hoff

// kA smem float-index layout (two sides)
#define XST  136
#define WST  68
#define X1F  8704      // side1 X
#define W1F  17408     // 4352
#define W2F  21760     // 4352
#define KWF  26112     // 64
#define VOF  26176     // 64
#define REDF 26240     // 16 (8 per side)
#define ESF  26256     // 256 (128 per side)
#define SMTA ((26512)*4)
// kC smem float-index layout (V fp16 rows: 136 half-units = 272 B)
#define QF   4352      // after Vb (64*272 B = 17408 B = 4352 floats)
#define GF   4416
#define HHF  4480      // 128
#define SMTC ((4608)*4)

// ---------------- helpers ---------------------------------------------------
__device__ __forceinline__ uint32_t s2u(const void* p) {
    uint32_t a;
    asm("{ .reg .u64 t; cvta.to.shared.u64 t, %1; cvt.u32.u64 %0, t; }" : "=r"(a) : "l"(p));
    return a;
}
__device__ __forceinline__ void cpa16(uint32_t dst, const void* src) {
    asm volatile("cp.async.ca.shared.global [%0], [%1], 16;" :: "r"(dst), "l"(src));
}
__device__ __forceinline__ void cpa_wait() {
    asm volatile("cp.async.commit_group;");
    asm volatile("cp.async.wait_group 0;" ::: "memory");
}
__device__ __forceinline__ unsigned ordf(float f) {
    unsigned u = __float_as_uint(f);
    return (u & 0x80000000u) ? ~u : (u | 0x80000000u);
}
__device__ __forceinline__ float deord(unsigned u) {
    u = (u & 0x80000000u) ? (u & 0x7fffffffu) : ~u;
    return __uint_as_float(u);
}
__device__ __forceinline__ float siluf(float z) {
    return __fdividef(z, 1.f + __expf(-z));
}
__device__ __forceinline__ float tf32r(float f) {
    uint32_t r; asm("cvt.rna.tf32.f32 %0, %1;" : "=r"(r) : "f"(f));
    return __uint_as_float(r);
}
#define MMA_TF32(C, a0, a1, a2, a3, b0, b1)                                     \
    asm volatile("mma.sync.aligned.m16n8k8.row.col.f32.tf32.tf32.f32 "          \
        "{%0,%1,%2,%3}, {%4,%5,%6,%7}, {%8,%9}, {%0,%1,%2,%3};"                 \
        : "+f"((C)[0]), "+f"((C)[1]), "+f"((C)[2]), "+f"((C)[3])                \
        : "r"(a0), "r"(a1), "r"(a2), "r"(a3), "r"(b0), "r"(b1))

// ---------------- init: zero accumulators + fold BN + tf32-round weights ----
__global__ void k_init(const float* conv_w,
                       const float* key_w, const float* key_g, const float* key_b,
                       const float* key_m, const float* key_v,
                       const float* val_w, const float* val_g, const float* val_b,
                       const float* val_m, const float* val_v,
                       const float* half_w, const float* half_g, const float* half_b,
                       const float* half_m, const float* half_v) {
    int t = threadIdx.x;
    for (int i = t; i < 2*NB*CCH; i += 256) { g_sumx[i] = 0.f; g_cmax[i] = 0u; g_fea[i] = 0.f; }
    for (int i = t; i < 2*NB; i += 256) { g_Z[i] = 0.f; }
    for (int i = t; i < 4096; i += 256) {
        int o = i >> 6;
        g_convw_r[i] = tf32r(conv_w[i]);
        float vs = val_g[o] * rsqrtf(val_v[o] + EPSV);
        g_valw_r[i] = tf32r(val_w[i] * vs);
    }
    if (t < CCH) {
        float ks = key_g[0] * rsqrtf(key_v[0] + EPSV);
        g_keywf[t] = key_w[t] * ks;
        float vs = val_g[t] * rsqrtf(val_v[t] + EPSV);
        g_valoff[t] = val_b[t] - val_m[t] * vs;
        if (t == 0) g_sc[0] = key_b[0] - key_m[0] * ks;
        if (t == 1) {
            float hs = half_g[0] * rsqrtf(half_v[0] + EPSV);
            g_sc[1] = half_w[0] * hs;
            g_sc[2] = half_w[1] * hs;
            g_sc[3] = half_b[0] - half_m[0] * hs;
        }
    }
}

// ---- kA: BOTH sides per block. warps 0-7 = rgb, 8-15 = ir.
// Per side: conv GEMM (cmax), keylogit->es/Z, val GEMM -> V fp16.
// Cross-side fea: fea[out=1-s] += V_s . es_{1-s}  (es shared via smem).
__global__ void __launch_bounds__(512, 2)
kA(const float* __restrict__ xr, const float* __restrict__ xi) {
    extern __shared__ float sm[];
    int n = blockIdx.y;
    int p0 = blockIdx.x * TP;
    int t = threadIdx.x;
    int side = t >> 8, tt = t & 255;
    int lane = tt & 31, w8 = tt >> 5;
    float* Xs = sm + side * X1F;
    float* W1 = sm + W1F;
    float* W2 = sm + W2F;
    float* kw = sm + KWF;
    float* vo = sm + VOF;
    float* red = sm + REDF + side*8;
    float* ES  = sm + ESF;             // [side*128 + p]
    __half* VS = (__half*)Xs;          // overlays own X after GEMMs
    const float* x = (side == 0 ? xr : xi) + (size_t)n * CCH * HW + p0;
    int base = (side*NB + n) * CCH;

    // W1+W2 via cp.async (once per block, serves both sides)
    uint32_t w1u = s2u(sm + W1F);
    for (int f = t; f < 2176; f += 512) {
        if (f < 1088) {
            cpa16(w1u + (uint32_t)(((f >> 4)*WST + (f & 15)*4)*4), g_convw_r + (f << 2));
        } else {
            int g = f - 1088;
            cpa16(w1u + (uint32_t)(4352*4 + ((g >> 4)*WST + (g & 15)*4)*4), g_valw_r + (g << 2));
        }
    }
    // X raw LDG + exact channel sums + STS (per side)
    #pragma unroll
    for (int m = 0; m < 8; m++) {
        int c = w8 + 8*m;
        float4 v = *(const float4*)(x + (size_t)c*HW + lane*4);
        float ps = (v.x + v.y) + (v.z + v.w);
        #pragma unroll
        for (int k = 16; k >= 1; k >>= 1) ps += __shfl_xor_sync(0xffffffffu, ps, k);
        if (lane == 0) atomicAdd(&g_sumx[base + c], ps);
        *(float4*)(Xs + c*XST + lane*4) = v;
    }
    if (t < 64) { kw[t] = g_keywf[t]; vo[t] = g_valoff[t]; }
    cpa_wait();
    __syncthreads();

    int gid = lane >> 2, tid4 = lane & 3;
    int o0 = (w8 & 3) * 16, pb = (w8 >> 2) * 64;

    // ---- GEMM1: conv ----
    float C[8][4];
    #pragma unroll
    for (int nf = 0; nf < 8; nf++) { C[nf][0]=0.f; C[nf][1]=0.f; C[nf][2]=0.f; C[nf][3]=0.f; }
    #pragma unroll
    for (int kk = 0; kk < 8; kk++) {
        const float* wr = W1 + (o0 + gid)*WST + kk*8 + tid4;
        uint32_t a0 = __float_as_uint(wr[0]);
        uint32_t a1 = __float_as_uint(wr[8*WST]);
        uint32_t a2 = __float_as_uint(wr[4]);
        uint32_t a3 = __float_as_uint(wr[8*WST + 4]);
        const float* xb = Xs + (kk*8 + tid4)*XST + pb + gid;
        #pragma unroll
        for (int nf = 0; nf < 8; nf++) {
            uint32_t b0 = __float_as_uint(xb[nf*8]);
            uint32_t b1 = __float_as_uint(xb[nf*8 + 4*XST]);
            MMA_TF32(C[nf], a0, a1, a2, a3, b0, b1);
        }
    }
    // channel max from frags (bias added in k_mid)
    {
        float mx0 = -1e30f, mx1 = -1e30f;
        #pragma unroll
        for (int nf = 0; nf < 8; nf++) {
            mx0 = fmaxf(mx0, fmaxf(C[nf][0], C[nf][1]));
            mx1 = fmaxf(mx1, fmaxf(C[nf][2], C[nf][3]));
        }
        mx0 = fmaxf(mx0, __shfl_xor_sync(0xffffffffu, mx0, 1));
        mx0 = fmaxf(mx0, __shfl_xor_sync(0xffffffffu, mx0, 2));
        mx1 = fmaxf(mx1, __shfl_xor_sync(0xffffffffu, mx1, 1));
        mx1 = fmaxf(mx1, __shfl_xor_sync(0xffffffffu, mx1, 2));
        if (tid4 == 0) {
            atomicMax(&g_cmax[base + o0 + gid], ordf(mx0));
            atomicMax(&g_cmax[base + o0 + gid + 8], ordf(mx1));
        }
    }

    // ---- GEMM2: val (reuse own Xs) ----
    #pragma unroll
    for (int nf = 0; nf < 8; nf++) { C[nf][0]=0.f; C[nf][1]=0.f; C[nf][2]=0.f; C[nf][3]=0.f; }
    #pragma unroll
    for (int kk = 0; kk < 8; kk++) {
        const float* wr = W2 + (o0 + gid)*WST + kk*8 + tid4;
        uint32_t a0 = __float_as_uint(wr[0]);
        uint32_t a1 = __float_as_uint(wr[8*WST]);
        uint32_t a2 = __float_as_uint(wr[4]);
        uint32_t a3 = __float_as_uint(wr[8*WST + 4]);
        const float* xb = Xs + (kk*8 + tid4)*XST + pb + gid;
        #pragma unroll
        for (int nf = 0; nf < 8; nf++) {
            uint32_t b0 = __float_as_uint(xb[nf*8]);
            uint32_t b1 = __float_as_uint(xb[nf*8 + 4*XST]);
            MMA_TF32(C[nf], a0, a1, a2, a3, b0, b1);
        }
    }
    float off0 = vo[o0 + gid], off1 = vo[o0 + gid + 8];

    // key logit -> es = exp(silu(z)) (no max subtraction; z bounded) + Z partial
    {
        int p = tt >> 1, h = tt & 1;
        float z = 0.f;
        #pragma unroll 8
        for (int c = 32*h; c < 32*h + 32; c++) z = fmaf(kw[c], Xs[c*XST + p], z);
        z += __shfl_xor_sync(0xffffffffu, z, 1);
        z += g_sc[0];
        float e = __expf(siluf(z));
        if (h == 0) ES[side*128 + p] = e;
        float zp = (h == 0) ? e : 0.f;
        #pragma unroll
        for (int k = 16; k >= 1; k >>= 1) zp += __shfl_xor_sync(0xffffffffu, zp, k);
        if (lane == 0) red[w8] = zp;
    }
    __syncthreads();   // both sides' ES/red ready; ALL X reads complete
    if (tt == 0) {
        float zs = (red[0] + red[1]) + (red[2] + red[3])
                 + (red[4] + red[5]) + (red[6] + red[7]);
        atomicAdd(&g_Z[side*NB + n], zs);
    }
    // silu + fp16 pack into own VS (stride 136 half units = 272 B rows)
    #pragma unroll
    for (int nf = 0; nf < 8; nf++) {
        int pp = pb + nf*8 + 2*tid4;
        __half2 h0 = __floats2half2_rn(siluf(C[nf][0] + off0), siluf(C[nf][1] + off0));
        __half2 h1 = __floats2half2_rn(siluf(C[nf][2] + off1), siluf(C[nf][3] + off1));
        *(__half2*)(VS + (o0 + gid)*136 + pp)     = h0;
        *(__half2*)(VS + (o0 + gid + 8)*136 + pp) = h1;
    }
    // in-side barrier: VS complete for this side's 256 threads
    asm volatile("bar.sync %0, %1;" :: "r"(side + 1), "r"(256) : "memory");

    // coalesced V write (own side)
    __half* gv = g_V + (size_t)((side*NB + n) * CCH) * HW + p0;
    #pragma unroll
    for (int i = tt; i < 2048; i += 256) {
        int c = i >> 5, u = i & 31;
        uint2 d = *(uint2*)(VS + c*136 + u*4);
        *(uint2*)(gv + (size_t)c*HW + u*4) = d;
    }
    // fea[out = 1-side][c] += sum_p V_side[c][p] * es_{1-side}[p]
    const float* ESo = sm + ESF + (1 - side)*128;
    float2 e0 = *(const float2*)(ESo + 2*lane);
    float2 e1 = *(const float2*)(ESo + 64 + 2*lane);
    int baseo = ((1 - side)*NB + n) * CCH;
    #pragma unroll
    for (int i = 0; i < 8; i++) {
        int c = w8 + 8*i;
        float2 v0 = __half22float2(*(const __half2*)(VS + c*136 + 2*lane));
        float2 v1 = __half22float2(*(const __half2*)(VS + c*136 + 64 + 2*lane));
        float fs = fmaf(v0.x, e0.x, fmaf(v0.y, e0.y, fmaf(v1.x, e1.x, v1.y * e1.y)));
        #pragma unroll
        for (int k = 16; k >= 1; k >>= 1) fs += __shfl_xor_sync(0xffffffffu, fs, k);
        if (lane == 0) atomicAdd(&g_fea[baseo + c], fs);
    }
}

// ---------------- mid: channel softmaxes ------------------------------------
__device__ __forceinline__ float blockmax64(float v, float* tmp) {
    tmp[threadIdx.x] = v; __syncthreads();
    for (int k = 32; k >= 1; k >>= 1) {
        if (threadIdx.x < k) tmp[threadIdx.x] = fmaxf(tmp[threadIdx.x], tmp[threadIdx.x + k]);
        __syncthreads();
    }
    float r = tmp[0]; __syncthreads(); return r;
}
__device__ __forceinline__ float blocksum64(float v, float* tmp) {
    tmp[threadIdx.x] = v; __syncthreads();
    for (int k = 32; k >= 1; k >>= 1) {
        if (threadIdx.x < k) tmp[threadIdx.x] += tmp[threadIdx.x + k];
        __syncthreads();
    }
    float r = tmp[0]; __syncthreads(); return r;
}

__global__ void k_mid(const float* __restrict__ conv_w, const float* __restrict__ conv_b) {
    int s = blockIdx.x, n = blockIdx.y, o = threadIdx.x;
    __shared__ float sx[64], tmp[64];
    int base = (s*NB + n) * CCH;
    sx[o] = g_sumx[base + o] * (1.f / (float)HW);
    __syncthreads();
    float mean = conv_b[o];
    for (int c = 0; c < 64; c++) mean = fmaf(sx[c], conv_w[o*64 + c], mean);
    float mx = deord(g_cmax[base + o]) + conv_b[o];

    float m1 = blockmax64(mean, tmp);
    float e1 = expf(mean - m1);
    float s1 = blocksum64(e1, tmp);
    g_avg[base + o] = e1 / s1;

    float m2 = blockmax64(mx, tmp);
    float e2 = expf(mx - m2);
    float s2 = blocksum64(e2, tmp);
    g_msm[base + o] = e2 / s2;
}

// ---------------- gate: fea/Z -> convb -> LN -> sigmoid --------------------
__global__ void k_gate(const float* __restrict__ convb_w,
                       const float* __restrict__ ln_g, const float* __restrict__ ln_b) {
    int so = blockIdx.x, n = blockIdx.y, o = threadIdx.x;
    __shared__ float ff[64], tmp[64];
    int base = (so*NB + n) * CCH;
    float Z = g_Z[so*NB + n];            // softmax denominator of MY key
    ff[o] = g_fea[base + o] / Z;         // fea already cross-paired in kA
    __syncthreads();
    float v = 0.f;
    for (int c = 0; c < 64; c++) v = fmaf(ff[c], convb_w[o*64 + c], v);
    float mu = blocksum64(v, tmp) * (1.f/64.f);
    float d = v - mu;
    float var = blocksum64(d*d, tmp) * (1.f/64.f);
    float gz = d * rsqrtf(var + EPSV) * ln_g[o] + ln_b[o];
    g_gate[base + o] = 1.f / (1.f + expf(-gz));
}

// ---- kC: streaming epilogue — half from V_other, out = gate*half + me -----
__global__ void __launch_bounds__(256)
kC(const float* __restrict__ xr, const float* __restrict__ xi,
   float* __restrict__ out) {
    extern __shared__ float sm[];
    __half* Vb = (__half*)sm;
    float* q  = sm + QF;
    float* gt = sm + GF;
    float* hh = sm + HHF;
    int so = blockIdx.z, n = blockIdx.y, sx = 1 - so;
    int p0 = blockIdx.x * TP;
    int t = threadIdx.x;
    int base2 = (so*NB + n) * CCH;
    const __half* gv = g_V + (size_t)((sx*NB + n) * CCH) * HW + p0;
    const float* x = (so == 0 ? xr : xi) + (size_t)n * CCH * HW + p0;
    float* o_b = out + (((size_t)(so*NB + n)) * CCH << 16) + p0;

    uint32_t vbu = s2u(Vb);
    #pragma unroll
    for (int j = 0; j < 4; j++) {
        int f = t + 256*j;
        int c = f >> 4, k = f & 15;
        cpa16(vbu + (uint32_t)(c*272 + k*16), gv + (size_t)c*HW + k*8);
    }
    if (t < 64) {
        q[t]  = g_sc[1]*g_avg[base2 + t] + g_sc[2]*g_msm[base2 + t];
        gt[t] = g_gate[base2 + t];
    }
    cpa_wait();
    __syncthreads();

    // half: 4 threads per pixel-pair (pq = t>>2, ch quarter h = t&3)
    {
        int pq = t >> 2, h = t & 3;
        float sa0 = 0.f, sa1 = 0.f;
        #pragma unroll 8
        for (int i = 0; i < 16; i++) {
            int c = h + 4*i;
            float2 vf = __half22float2(*(const __half2*)(Vb + c*136 + 2*pq));
            float qc = q[c];
            sa0 = fmaf(qc, vf.x, sa0);
            sa1 = fmaf(qc, vf.y, sa1);
        }
        sa0 += __shfl_xor_sync(0xffffffffu, sa0, 1);
        sa0 += __shfl_xor_sync(0xffffffffu, sa0, 2);
        sa1 += __shfl_xor_sync(0xffffffffu, sa1, 1);
        sa1 += __shfl_xor_sync(0xffffffffu, sa1, 2);
        if (h == 0) {
            hh[2*pq]     = siluf(sa0 + g_sc[3]);
            hh[2*pq + 1] = siluf(sa1 + g_sc[3]);
        }
    }
    __syncthreads();

    // out stream: 2048 float4 per block, fully coalesced
    #pragma unroll
    for (int i = 0; i < 8; i++) {
        int idx = t + 256*i;
        int c = idx >> 5, u = idx & 31;
        float g = gt[c];
        float4 m4 = *(const float4*)(x + (size_t)c*HW + u*4);
        const float* hp = hh + u*4;
        float4 o4;
        o4.x = fmaf(g, hp[0], m4.x);
        o4.y = fmaf(g, hp[1], m4.y);
        o4.z = fmaf(g, hp[2], m4.z);
        o4.w = fmaf(g, hp[3], m4.w);
        *(float4*)(o_b + ((size_t)c << 16) + u*4) = o4;
    }
}

// ---------------- launch ---------------------------------------------------
extern "C" void kernel_launch(void* const* d_in, const int* in_sizes, int n_in,
                              void* d_out, int out_size) {
    const float* rgb    = (const float*)d_in[0];
    const float* ir     = (const float*)d_in[1];
    const float* conv_w = (const float*)d_in[2];
    const float* conv_b = (const float*)d_in[3];
    const float* key_w  = (const float*)d_in[4];
    const float* key_g  = (const float*)d_in[5];
    const float* key_b  = (const float*)d_in[6];
    const float* key_m  = (const float*)d_in[7];
    const float* key_v  = (const float*)d_in[8];
    const float* val_w  = (const float*)d_in[9];
    const float* val_g  = (const float*)d_in[10];
    const float* val_b  = (const float*)d_in[11];
    const float* val_m  = (const float*)d_in[12];
    const float* val_v  = (const float*)d_in[13];
    const float* convb_w= (const float*)d_in[14];
    const float* half_w = (const float*)d_in[15];
    const float* half_g = (const float*)d_in[16];
    const float* half_b = (const float*)d_in[17];
    const float* half_m = (const float*)d_in[18];
    const float* half_v = (const float*)d_in[19];
    const float* ln_g   = (const float*)d_in[20];
    const float* ln_b   = (const float*)d_in[21];
    float* out = (float*)d_out;

    cudaFuncSetAttribute(kA, cudaFuncAttributeMaxDynamicSharedMemorySize, SMTA);
    cudaFuncSetAttribute(kC, cudaFuncAttributeMaxDynamicSharedMemorySize, SMTC);

    k_init<<<1, 256>>>(conv_w, key_w, key_g, key_b, key_m, key_v,
                       val_w, val_g, val_b, val_m, val_v,
                       half_w, half_g, half_b, half_m, half_v);
    kA<<<dim3(HW / TP, NB, 1), 512, SMTA>>>(rgb, ir);
    k_mid<<<dim3(2, NB), 64>>>(conv_w, conv_b);
    k_gate<<<dim3(2, NB), 64>>>(convb_w, ln_g, ln_b);
    kC<<<dim3(HW / TP, NB, 2), 256, SMTC>>>(rgb, ir, out);
}

// round 17
// speedup vs baseline: 1.9210x; 1.0188x over previous
#include <cuda_runtime.h>
#include <cuda_fp16.h>
#include <math.h>
#include <stdint.h>

#define EPSV 1e-5f
#define HW   65536
#define CCH  64
#define NB   8
#define TP   128

// ---------------- scratch (device globals; no runtime allocation) ----------
__device__ float    g_sumx[2*NB*CCH];
__device__ unsigned g_cmax[2*NB*CCH];
__device__ float    g_fea [2*NB*CCH];
__device__ float    g_Z   [2*NB];
__device__ float    g_avg [2*NB*CCH];
__device__ float    g_msm [2*NB*CCH];
__device__ float    g_gate[2*NB*CCH];
__device__ __align__(16) __half g_V[(size_t)2*NB*CCH*HW];  // 134 MB fp16 V
__device__ __align__(16) float g_convw_r[CCH*CCH];  // conv_w, tf32-rounded [o][k]
__device__ __align__(16) float g_valw_r[CCH*CCH];   // val_w*BNscale, tf32-rounded [o][k]
__device__ float    g_keywf[CCH];
__device__ float    g_valoff[CCH];
__device__ float    g_sc[4];             // keyoff, hw0, hw1, hoff

// kA smem float-index layout (two sides)
#define XST  136
#define WST  68
#define X1F  8704      // side1 X
#define W1F  17408     // 4352
#define W2F  21760     // 4352
#define KWF  26112     // 64
#define VOF  26176     // 64
#define REDF 26240     // 16 (8 per side)
#define ESF  26256     // 256 (128 per side)
#define SMTA ((26512)*4)
// kC smem float-index layout (V fp16 rows: 136 half-units = 272 B)
#define QF   4352      // after Vb (64*272 B = 17408 B = 4352 floats)
#define GF   4416
#define HHF  4480      // 128
#define SMTC ((4608)*4)

// ---------------- helpers ---------------------------------------------------
__device__ __forceinline__ uint32_t s2u(const void* p) {
    uint32_t a;
    asm("{ .reg .u64 t; cvta.to.shared.u64 t, %1; cvt.u32.u64 %0, t; }" : "=r"(a) : "l"(p));
    return a;
}
__device__ __forceinline__ void cpa16(uint32_t dst, const void* src) {
    asm volatile("cp.async.ca.shared.global [%0], [%1], 16;" :: "r"(dst), "l"(src));
}
__device__ __forceinline__ void cpa_wait() {
    asm volatile("cp.async.commit_group;");
    asm volatile("cp.async.wait_group 0;" ::: "memory");
}
__device__ __forceinline__ unsigned ordf(float f) {
    unsigned u = __float_as_uint(f);
    return (u & 0x80000000u) ? ~u : (u | 0x80000000u);
}
__device__ __forceinline__ float deord(unsigned u) {
    u = (u & 0x80000000u) ? (u & 0x7fffffffu) : ~u;
    return __uint_as_float(u);
}
__device__ __forceinline__ float siluf(float z) {
    return __fdividef(z, 1.f + __expf(-z));
}
__device__ __forceinline__ float tf32r(float f) {
    uint32_t r; asm("cvt.rna.tf32.f32 %0, %1;" : "=r"(r) : "f"(f));
    return __uint_as_float(r);
}
#define MMA_TF32(C, a0, a1, a2, a3, b0, b1)                                     \
    asm volatile("mma.sync.aligned.m16n8k8.row.col.f32.tf32.tf32.f32 "          \
        "{%0,%1,%2,%3}, {%4,%5,%6,%7}, {%8,%9}, {%0,%1,%2,%3};"                 \
        : "+f"((C)[0]), "+f"((C)[1]), "+f"((C)[2]), "+f"((C)[3])                \
        : "r"(a0), "r"(a1), "r"(a2), "r"(a3), "r"(b0), "r"(b1))

// ---------------- init: zero accumulators + fold BN + tf32-round weights ----
__global__ void k_init(const float* conv_w,
                       const float* key_w, const float* key_g, const float* key_b,
                       const float* key_m, const float* key_v,
                       const float* val_w, const float* val_g, const float* val_b,
                       const float* val_m, const float* val_v,
                       const float* half_w, const float* half_g, const float* half_b,
                       const float* half_m, const float* half_v) {
    int t = threadIdx.x;
    for (int i = t; i < 2*NB*CCH; i += 256) { g_sumx[i] = 0.f; g_cmax[i] = 0u; g_fea[i] = 0.f; }
    for (int i = t; i < 2*NB; i += 256) { g_Z[i] = 0.f; }
    for (int i = t; i < 4096; i += 256) {
        int o = i >> 6;
        g_convw_r[i] = tf32r(conv_w[i]);
        float vs = val_g[o] * rsqrtf(val_v[o] + EPSV);
        g_valw_r[i] = tf32r(val_w[i] * vs);
    }
    if (t < CCH) {
        float ks = key_g[0] * rsqrtf(key_v[0] + EPSV);
        g_keywf[t] = key_w[t] * ks;
        float vs = val_g[t] * rsqrtf(val_v[t] + EPSV);
        g_valoff[t] = val_b[t] - val_m[t] * vs;
        if (t == 0) g_sc[0] = key_b[0] - key_m[0] * ks;
        if (t == 1) {
            float hs = half_g[0] * rsqrtf(half_v[0] + EPSV);
            g_sc[1] = half_w[0] * hs;
            g_sc[2] = half_w[1] * hs;
            g_sc[3] = half_b[0] - half_m[0] * hs;
        }
    }
}

// ---- kA: BOTH sides per block. warps 0-7 = rgb, 8-15 = ir.
// Warp tile: 32 out-ch (o0 = 32*(w8&1), two m16 subtiles) x 32 px (pb = 32*(w8>>1)).
// B-frags shared across the two row subtiles -> 16 LDS per kk (vs 20).
__global__ void __launch_bounds__(512, 2)
kA(const float* __restrict__ xr, const float* __restrict__ xi) {
    extern __shared__ float sm[];
    int n = blockIdx.y;
    int p0 = blockIdx.x * TP;
    int t = threadIdx.x;
    int side = t >> 8, tt = t & 255;
    int lane = tt & 31, w8 = tt >> 5;
    float* Xs = sm + side * X1F;
    float* W1 = sm + W1F;
    float* W2 = sm + W2F;
    float* kw = sm + KWF;
    float* vo = sm + VOF;
    float* red = sm + REDF + side*8;
    float* ES  = sm + ESF;             // [side*128 + p]
    __half* VS = (__half*)Xs;          // overlays own X after GEMMs
    const float* x = (side == 0 ? xr : xi) + (size_t)n * CCH * HW + p0;
    int base = (side*NB + n) * CCH;

    // W1+W2 via cp.async (once per block, serves both sides)
    uint32_t w1u = s2u(sm + W1F);
    for (int f = t; f < 2176; f += 512) {
        if (f < 1088) {
            cpa16(w1u + (uint32_t)(((f >> 4)*WST + (f & 15)*4)*4), g_convw_r + (f << 2));
        } else {
            int g = f - 1088;
            cpa16(w1u + (uint32_t)(4352*4 + ((g >> 4)*WST + (g & 15)*4)*4), g_valw_r + (g << 2));
        }
    }
    // X raw LDG + exact channel sums + STS (per side)
    #pragma unroll
    for (int m = 0; m < 8; m++) {
        int c = w8 + 8*m;
        float4 v = *(const float4*)(x + (size_t)c*HW + lane*4);
        float ps = (v.x + v.y) + (v.z + v.w);
        #pragma unroll
        for (int k = 16; k >= 1; k >>= 1) ps += __shfl_xor_sync(0xffffffffu, ps, k);
        if (lane == 0) atomicAdd(&g_sumx[base + c], ps);
        *(float4*)(Xs + c*XST + lane*4) = v;
    }
    if (t < 64) { kw[t] = g_keywf[t]; vo[t] = g_valoff[t]; }
    cpa_wait();
    __syncthreads();

    int gid = lane >> 2, tid4 = lane & 3;
    int o0 = (w8 & 1) * 32, pb = (w8 >> 1) * 32;

    // ---- GEMM1: conv ----  C[i*4+nf]: i row-subtile (16 ch), nf px-subtile (8 px)
    float C[8][4];
    #pragma unroll
    for (int nf = 0; nf < 8; nf++) { C[nf][0]=0.f; C[nf][1]=0.f; C[nf][2]=0.f; C[nf][3]=0.f; }
    #pragma unroll
    for (int kk = 0; kk < 8; kk++) {
        const float* wr = W1 + (o0 + gid)*WST + kk*8 + tid4;
        uint32_t a00 = __float_as_uint(wr[0]);
        uint32_t a01 = __float_as_uint(wr[8*WST]);
        uint32_t a02 = __float_as_uint(wr[4]);
        uint32_t a03 = __float_as_uint(wr[8*WST + 4]);
        uint32_t a10 = __float_as_uint(wr[16*WST]);
        uint32_t a11 = __float_as_uint(wr[24*WST]);
        uint32_t a12 = __float_as_uint(wr[16*WST + 4]);
        uint32_t a13 = __float_as_uint(wr[24*WST + 4]);
        const float* xb = Xs + (kk*8 + tid4)*XST + pb + gid;
        #pragma unroll
        for (int nf = 0; nf < 4; nf++) {
            uint32_t b0 = __float_as_uint(xb[nf*8]);
            uint32_t b1 = __float_as_uint(xb[nf*8 + 4*XST]);
            MMA_TF32(C[nf],     a00, a01, a02, a03, b0, b1);
            MMA_TF32(C[4 + nf], a10, a11, a12, a13, b0, b1);
        }
    }
    // channel max from frags (bias added later in k_small)
    #pragma unroll
    for (int i = 0; i < 2; i++) {
        float mx0 = -1e30f, mx1 = -1e30f;
        #pragma unroll
        for (int nf = 0; nf < 4; nf++) {
            mx0 = fmaxf(mx0, fmaxf(C[i*4 + nf][0], C[i*4 + nf][1]));
            mx1 = fmaxf(mx1, fmaxf(C[i*4 + nf][2], C[i*4 + nf][3]));
        }
        mx0 = fmaxf(mx0, __shfl_xor_sync(0xffffffffu, mx0, 1));
        mx0 = fmaxf(mx0, __shfl_xor_sync(0xffffffffu, mx0, 2));
        mx1 = fmaxf(mx1, __shfl_xor_sync(0xffffffffu, mx1, 1));
        mx1 = fmaxf(mx1, __shfl_xor_sync(0xffffffffu, mx1, 2));
        if (tid4 == 0) {
            atomicMax(&g_cmax[base + o0 + 16*i + gid], ordf(mx0));
            atomicMax(&g_cmax[base + o0 + 16*i + gid + 8], ordf(mx1));
        }
    }

    // ---- GEMM2: val (reuse own Xs, same B-frag pattern) ----
    #pragma unroll
    for (int nf = 0; nf < 8; nf++) { C[nf][0]=0.f; C[nf][1]=0.f; C[nf][2]=0.f; C[nf][3]=0.f; }
    #pragma unroll
    for (int kk = 0; kk < 8; kk++) {
        const float* wr = W2 + (o0 + gid)*WST + kk*8 + tid4;
        uint32_t a00 = __float_as_uint(wr[0]);
        uint32_t a01 = __float_as_uint(wr[8*WST]);
        uint32_t a02 = __float_as_uint(wr[4]);
        uint32_t a03 = __float_as_uint(wr[8*WST + 4]);
        uint32_t a10 = __float_as_uint(wr[16*WST]);
        uint32_t a11 = __float_as_uint(wr[24*WST]);
        uint32_t a12 = __float_as_uint(wr[16*WST + 4]);
        uint32_t a13 = __float_as_uint(wr[24*WST + 4]);
        const float* xb = Xs + (kk*8 + tid4)*XST + pb + gid;
        #pragma unroll
        for (int nf = 0; nf < 4; nf++) {
            uint32_t b0 = __float_as_uint(xb[nf*8]);
            uint32_t b1 = __float_as_uint(xb[nf*8 + 4*XST]);
            MMA_TF32(C[nf],     a00, a01, a02, a03, b0, b1);
            MMA_TF32(C[4 + nf], a10, a11, a12, a13, b0, b1);
        }
    }
    float off00 = vo[o0 + gid],      off01 = vo[o0 + gid + 8];
    float off10 = vo[o0 + 16 + gid], off11 = vo[o0 + 24 + gid];

    // key logit -> es = exp(silu(z)) (no max subtraction; z bounded) + Z partial
    {
        int p = tt >> 1, h = tt & 1;
        float z = 0.f;
        #pragma unroll 8
        for (int c = 32*h; c < 32*h + 32; c++) z = fmaf(kw[c], Xs[c*XST + p], z);
        z += __shfl_xor_sync(0xffffffffu, z, 1);
        z += g_sc[0];
        float e = __expf(siluf(z));
        if (h == 0) ES[side*128 + p] = e;
        float zp = (h == 0) ? e : 0.f;
        #pragma unroll
        for (int k = 16; k >= 1; k >>= 1) zp += __shfl_xor_sync(0xffffffffu, zp, k);
        if (lane == 0) red[w8] = zp;
    }
    __syncthreads();   // both sides' ES/red ready; ALL X reads complete
    if (tt == 0) {
        float zs = (red[0] + red[1]) + (red[2] + red[3])
                 + (red[4] + red[5]) + (red[6] + red[7]);
        atomicAdd(&g_Z[side*NB + n], zs);
    }
    // silu + fp16 pack into own VS (stride 136 half units = 272 B rows)
    #pragma unroll
    for (int i = 0; i < 2; i++) {
        float offA = (i == 0) ? off00 : off10;
        float offB = (i == 0) ? off01 : off11;
        #pragma unroll
        for (int nf = 0; nf < 4; nf++) {
            int pp = pb + nf*8 + 2*tid4;
            float* Cc = C[i*4 + nf];
            __half2 h0 = __floats2half2_rn(siluf(Cc[0] + offA), siluf(Cc[1] + offA));
            __half2 h1 = __floats2half2_rn(siluf(Cc[2] + offB), siluf(Cc[3] + offB));
            *(__half2*)(VS + (o0 + 16*i + gid)*136 + pp)     = h0;
            *(__half2*)(VS + (o0 + 16*i + gid + 8)*136 + pp) = h1;
        }
    }
    // in-side barrier: VS complete for this side's 256 threads
    asm volatile("bar.sync %0, %1;" :: "r"(side + 1), "r"(256) : "memory");

    // coalesced V write (own side)
    __half* gv = g_V + (size_t)((side*NB + n) * CCH) * HW + p0;
    #pragma unroll
    for (int i = tt; i < 2048; i += 256) {
        int c = i >> 5, u = i & 31;
        uint2 d = *(uint2*)(VS + c*136 + u*4);
        *(uint2*)(gv + (size_t)c*HW + u*4) = d;
    }
    // fea[out = 1-side][c] += sum_p V_side[c][p] * es_{1-side}[p]
    const float* ESo = sm + ESF + (1 - side)*128;
    float2 e0 = *(const float2*)(ESo + 2*lane);
    float2 e1 = *(const float2*)(ESo + 64 + 2*lane);
    int baseo = ((1 - side)*NB + n) * CCH;
    #pragma unroll
    for (int i = 0; i < 8; i++) {
        int c = w8 + 8*i;
        float2 v0 = __half22float2(*(const __half2*)(VS + c*136 + 2*lane));
        float2 v1 = __half22float2(*(const __half2*)(VS + c*136 + 64 + 2*lane));
        float fs = fmaf(v0.x, e0.x, fmaf(v0.y, e0.y, fmaf(v1.x, e1.x, v1.y * e1.y)));
        #pragma unroll
        for (int k = 16; k >= 1; k >>= 1) fs += __shfl_xor_sync(0xffffffffu, fs, k);
        if (lane == 0) atomicAdd(&g_fea[baseo + c], fs);
    }
}

// ---------------- k_small: mid (softmaxes) + gate (LN/sigmoid) merged -------
__device__ __forceinline__ float blockmax64(float v, float* tmp) {
    tmp[threadIdx.x] = v; __syncthreads();
    for (int k = 32; k >= 1; k >>= 1) {
        if (threadIdx.x < k) tmp[threadIdx.x] = fmaxf(tmp[threadIdx.x], tmp[threadIdx.x + k]);
        __syncthreads();
    }
    float r = tmp[0]; __syncthreads(); return r;
}
__device__ __forceinline__ float blocksum64(float v, float* tmp) {
    tmp[threadIdx.x] = v; __syncthreads();
    for (int k = 32; k >= 1; k >>= 1) {
        if (threadIdx.x < k) tmp[threadIdx.x] += tmp[threadIdx.x + k];
        __syncthreads();
    }
    float r = tmp[0]; __syncthreads(); return r;
}

__global__ void k_small(const float* __restrict__ conv_w, const float* __restrict__ conv_b,
                        const float* __restrict__ convb_w,
                        const float* __restrict__ ln_g, const float* __restrict__ ln_b) {
    __shared__ float sx[64], tmp[64];
    int role = blockIdx.x >> 4;
    int id = blockIdx.x & 15;
    int s = id & 1, n = id >> 1;
    int o = threadIdx.x;
    int base = (s*NB + n) * CCH;
    if (role == 0) {   // mid: channel softmaxes
        sx[o] = g_sumx[base + o] * (1.f / (float)HW);
        __syncthreads();
        float mean = conv_b[o];
        for (int c = 0; c < 64; c++) mean = fmaf(sx[c], conv_w[o*64 + c], mean);
        float mx = deord(g_cmax[base + o]) + conv_b[o];

        float m1 = blockmax64(mean, tmp);
        float e1 = expf(mean - m1);
        float s1 = blocksum64(e1, tmp);
        g_avg[base + o] = e1 / s1;

        float m2 = blockmax64(mx, tmp);
        float e2 = expf(mx - m2);
        float s2 = blocksum64(e2, tmp);
        g_msm[base + o] = e2 / s2;
    } else {           // gate: fea/Z -> convb -> LN -> sigmoid
        float Z = g_Z[s*NB + n];
        sx[o] = g_fea[base + o] / Z;
        __syncthreads();
        float v = 0.f;
        for (int c = 0; c < 64; c++) v = fmaf(sx[c], convb_w[o*64 + c], v);
        float mu = blocksum64(v, tmp) * (1.f/64.f);
        float d = v - mu;
        float var = blocksum64(d*d, tmp) * (1.f/64.f);
        float gz = d * rsqrtf(var + EPSV) * ln_g[o] + ln_b[o];
        g_gate[base + o] = 1.f / (1.f + expf(-gz));
    }
}

// ---- kC: streaming epilogue — half from V_other, out = gate*half + me -----
__global__ void __launch_bounds__(256)
kC(const float* __restrict__ xr, const float* __restrict__ xi,
   float* __restrict__ out) {
    extern __shared__ float sm[];
    __half* Vb = (__half*)sm;
    float* q  = sm + QF;
    float* gt = sm + GF;
    float* hh = sm + HHF;
    int so = blockIdx.z, n = blockIdx.y, sx = 1 - so;
    int p0 = blockIdx.x * TP;
    int t = threadIdx.x;
    int base2 = (so*NB + n) * CCH;
    const __half* gv = g_V + (size_t)((sx*NB + n) * CCH) * HW + p0;
    const float* x = (so == 0 ? xr : xi) + (size_t)n * CCH * HW + p0;
    float* o_b = out + (((size_t)(so*NB + n)) * CCH << 16) + p0;

    uint32_t vbu = s2u(Vb);
    #pragma unroll
    for (int j = 0; j < 4; j++) {
        int f = t + 256*j;
        int c = f >> 4, k = f & 15;
        cpa16(vbu + (uint32_t)(c*272 + k*16), gv + (size_t)c*HW + k*8);
    }
    if (t < 64) {
        q[t]  = g_sc[1]*g_avg[base2 + t] + g_sc[2]*g_msm[base2 + t];
        gt[t] = g_gate[base2 + t];
    }
    cpa_wait();
    __syncthreads();

    // half: 4 threads per pixel-pair (pq = t>>2, ch quarter h = t&3)
    {
        int pq = t >> 2, h = t & 3;
        float sa0 = 0.f, sa1 = 0.f;
        #pragma unroll 8
        for (int i = 0; i < 16; i++) {
            int c = h + 4*i;
            float2 vf = __half22float2(*(const __half2*)(Vb + c*136 + 2*pq));
            float qc = q[c];
            sa0 = fmaf(qc, vf.x, sa0);
            sa1 = fmaf(qc, vf.y, sa1);
        }
        sa0 += __shfl_xor_sync(0xffffffffu, sa0, 1);
        sa0 += __shfl_xor_sync(0xffffffffu, sa0, 2);
        sa1 += __shfl_xor_sync(0xffffffffu, sa1, 1);
        sa1 += __shfl_xor_sync(0xffffffffu, sa1, 2);
        if (h == 0) {
            hh[2*pq]     = siluf(sa0 + g_sc[3]);
            hh[2*pq + 1] = siluf(sa1 + g_sc[3]);
        }
    }
    __syncthreads();

    // out stream: 2048 float4 per block, fully coalesced
    #pragma unroll
    for (int i = 0; i < 8; i++) {
        int idx = t + 256*i;
        int c = idx >> 5, u = idx & 31;
        float g = gt[c];
        float4 m4 = *(const float4*)(x + (size_t)c*HW + u*4);
        const float* hp = hh + u*4;
        float4 o4;
        o4.x = fmaf(g, hp[0], m4.x);
        o4.y = fmaf(g, hp[1], m4.y);
        o4.z = fmaf(g, hp[2], m4.z);
        o4.w = fmaf(g, hp[3], m4.w);
        *(float4*)(o_b + ((size_t)c << 16) + u*4) = o4;
    }
}

// ---------------- launch ---------------------------------------------------
extern "C" void kernel_launch(void* const* d_in, const int* in_sizes, int n_in,
                              void* d_out, int out_size) {
    const float* rgb    = (const float*)d_in[0];
    const float* ir     = (const float*)d_in[1];
    const float* conv_w = (const float*)d_in[2];
    const float* conv_b = (const float*)d_in[3];
    const float* key_w  = (const float*)d_in[4];
    const float* key_g  = (const float*)d_in[5];
    const float* key_b  = (const float*)d_in[6];
    const float* key_m  = (const float*)d_in[7];
    const float* key_v  = (const float*)d_in[8];
    const float* val_w  = (const float*)d_in[9];
    const float* val_g  = (const float*)d_in[10];
    const float* val_b  = (const float*)d_in[11];
    const float* val_m  = (const float*)d_in[12];
    const float* val_v  = (const float*)d_in[13];
    const float* convb_w= (const float*)d_in[14];
    const float* half_w = (const float*)d_in[15];
    const float* half_g = (const float*)d_in[16];
    const float* half_b = (const float*)d_in[17];
    const float* half_m = (const float*)d_in[18];
    const float* half_v = (const float*)d_in[19];
    const float* ln_g   = (const float*)d_in[20];
    const float* ln_b   = (const float*)d_in[21];
    float* out = (float*)d_out;

    cudaFuncSetAttribute(kA, cudaFuncAttributeMaxDynamicSharedMemorySize, SMTA);
    cudaFuncSetAttribute(kC, cudaFuncAttributeMaxDynamicSharedMemorySize, SMTC);

    k_init<<<1, 256>>>(conv_w, key_w, key_g, key_b, key_m, key_v,
                       val_w, val_g, val_b, val_m, val_v,
                       half_w, half_g, half_b, half_m, half_v);
    kA<<<dim3(HW / TP, NB, 1), 512, SMTA>>>(rgb, ir);
    k_small<<<32, 64>>>(conv_w, conv_b, convb_w, ln_g, ln_b);
    kC<<<dim3(HW / TP, NB, 2), 256, SMTC>>>(rgb, ir, out);
}